// round 1
// baseline (speedup 1.0000x reference)
#include <cuda_runtime.h>

#define BB   8
#define SS   1024
#define DQKV 1024
#define NH   16
#define HE   64
#define DOUT 1024

// Scratch (allocation-free contract: __device__ globals)
__device__ float g_Q[BB*NH*SS*HE];
__device__ float g_K[BB*NH*SS*HE];
__device__ float g_V[BB*NH*SS*HE];
__device__ float g_ATT[BB*SS*NH*HE];

// ---------------------------------------------------------------------------
// Projection GEMM: X[B*S, QKV] @ W[h] -> Out[B,H,S,E]
// Each N-tile of 64 is exactly one head (E=64). 64x64x16 tiles, 4x4/thread.
// ---------------------------------------------------------------------------
__global__ __launch_bounds__(256) void proj_kernel(const float* __restrict__ X,
                                                   const float* __restrict__ W,
                                                   int which)
{
    __shared__ float As[16][64];
    __shared__ float Bs[16][64];
    float* Out = (which == 0) ? g_Q : (which == 1) ? g_K : g_V;

    const int h  = blockIdx.x;        // head == N tile
    const int m0 = blockIdx.y * 64;   // row tile of B*S
    const int tx = threadIdx.x, ty = threadIdx.y;
    const int tid = ty * 16 + tx;

    const int ar = tid >> 2;          // 0..63 : A tile row
    const int ak = (tid & 3) << 2;    // 0,4,8,12 : A tile k
    const int bk = tid >> 4;          // 0..15 : B tile k
    const int bj = (tid & 15) << 2;   // 0..60 : B tile n

    const float* Wh = W + h * DQKV * HE;

    float c[4][4] = {};

    for (int kk = 0; kk < DQKV; kk += 16) {
        float4 av = *(const float4*)(X + (m0 + ar) * DQKV + kk + ak);
        As[ak+0][ar] = av.x; As[ak+1][ar] = av.y;
        As[ak+2][ar] = av.z; As[ak+3][ar] = av.w;
        *(float4*)(&Bs[bk][bj]) = *(const float4*)(Wh + (kk + bk) * HE + bj);
        __syncthreads();
        #pragma unroll
        for (int k = 0; k < 16; k++) {
            float4 a4 = *(const float4*)(&As[k][ty*4]);
            float4 b4 = *(const float4*)(&Bs[k][tx*4]);
            float aa[4] = {a4.x, a4.y, a4.z, a4.w};
            float bb[4] = {b4.x, b4.y, b4.z, b4.w};
            #pragma unroll
            for (int i = 0; i < 4; i++)
                #pragma unroll
                for (int j = 0; j < 4; j++)
                    c[i][j] += aa[i] * bb[j];
        }
        __syncthreads();
    }

    #pragma unroll
    for (int i = 0; i < 4; i++) {
        int m = m0 + ty*4 + i;
        int b = m >> 10;
        int s = m & 1023;
        float4 v = make_float4(c[i][0], c[i][1], c[i][2], c[i][3]);
        *(float4*)(Out + (((b*NH + h)*SS + s)*HE) + tx*4) = v;
    }
}

// ---------------------------------------------------------------------------
// Flash-style attention: one CTA = (64 query rows, head h, batch b).
// Online softmax, K-tile and P share one padded smem buffer.
// Writes attended directly in concat layout [B, S, H*E].
// ---------------------------------------------------------------------------
__global__ __launch_bounds__(256) void attn_kernel()
{
    __shared__ float Qs[64*64];    // [r][k]
    __shared__ float KP[64*65];    // K tile [c][k] (pad 65), later P [r][c]
    __shared__ float Vs[64*64];    // [k][e]

    const int s0 = blockIdx.x * 64;
    const int h  = blockIdx.y;
    const int b  = blockIdx.z;
    const int tx = threadIdx.x, ty = threadIdx.y;
    const int tid = ty*16 + tx;
    const int lr  = tid >> 4;          // 0..15
    const int lc  = (tid & 15) << 2;   // 0..60

    const float* Qp = g_Q + (size_t)((b*NH + h)*SS + s0) * HE;
    const float* Kp = g_K + (size_t)((b*NH + h)*SS) * HE;
    const float* Vp = g_V + (size_t)((b*NH + h)*SS) * HE;

    const float scale = 0.03125f;  // 1/sqrt(1024)

    // load Q tile (pre-scaled)
    #pragma unroll
    for (int it = 0; it < 4; it++) {
        int r = lr + it*16;
        float4 v = *(const float4*)(Qp + r*HE + lc);
        Qs[r*64 + lc+0] = v.x * scale;
        Qs[r*64 + lc+1] = v.y * scale;
        Qs[r*64 + lc+2] = v.z * scale;
        Qs[r*64 + lc+3] = v.w * scale;
    }

    float o[4][4] = {};
    float mrow[4] = {-1e30f, -1e30f, -1e30f, -1e30f};
    float lsum[4] = {};

    for (int t = 0; t < SS/64; t++) {
        __syncthreads();   // previous iter done reading KP/Vs; Q store visible (t==0)
        // load K tile [c][k] (padded) and V tile [k][e]
        #pragma unroll
        for (int it = 0; it < 4; it++) {
            int r = lr + it*16;
            float4 kv = *(const float4*)(Kp + (t*64 + r)*HE + lc);
            KP[r*65 + lc+0] = kv.x; KP[r*65 + lc+1] = kv.y;
            KP[r*65 + lc+2] = kv.z; KP[r*65 + lc+3] = kv.w;
            float4 vv = *(const float4*)(Vp + (t*64 + r)*HE + lc);
            *(float4*)(&Vs[r*64 + lc]) = vv;
        }
        __syncthreads();

        // scores S = Q @ K^T (scaled already)
        float sc[4][4] = {};
        #pragma unroll 4
        for (int k = 0; k < 64; k++) {
            float aa[4], bb[4];
            #pragma unroll
            for (int i = 0; i < 4; i++) aa[i] = Qs[(ty*4+i)*64 + k];
            #pragma unroll
            for (int j = 0; j < 4; j++) bb[j] = KP[(tx*4+j)*65 + k];
            #pragma unroll
            for (int i = 0; i < 4; i++)
                #pragma unroll
                for (int j = 0; j < 4; j++)
                    sc[i][j] += aa[i] * bb[j];
        }

        // online softmax update (row reductions across the 16 tx lanes)
        #pragma unroll
        for (int i = 0; i < 4; i++) {
            float tm = fmaxf(fmaxf(sc[i][0], sc[i][1]), fmaxf(sc[i][2], sc[i][3]));
            #pragma unroll
            for (int off = 8; off >= 1; off >>= 1)
                tm = fmaxf(tm, __shfl_xor_sync(0xffffffffu, tm, off));
            float nm   = fmaxf(mrow[i], tm);
            float corr = __expf(mrow[i] - nm);
            float rs = 0.f;
            #pragma unroll
            for (int j = 0; j < 4; j++) {
                sc[i][j] = __expf(sc[i][j] - nm);
                rs += sc[i][j];
            }
            #pragma unroll
            for (int off = 8; off >= 1; off >>= 1)
                rs += __shfl_xor_sync(0xffffffffu, rs, off);
            lsum[i] = lsum[i]*corr + rs;
            mrow[i] = nm;
            #pragma unroll
            for (int j = 0; j < 4; j++) o[i][j] *= corr;
        }

        __syncthreads();   // all done reading K from KP
        // write P into KP
        #pragma unroll
        for (int i = 0; i < 4; i++)
            #pragma unroll
            for (int j = 0; j < 4; j++)
                KP[(ty*4+i)*65 + (tx*4+j)] = sc[i][j];
        __syncthreads();

        // O += P @ V
        #pragma unroll 4
        for (int k = 0; k < 64; k++) {
            float pp[4];
            #pragma unroll
            for (int i = 0; i < 4; i++) pp[i] = KP[(ty*4+i)*65 + k];
            float4 v4 = *(const float4*)(&Vs[k*64 + tx*4]);
            float vv[4] = {v4.x, v4.y, v4.z, v4.w};
            #pragma unroll
            for (int i = 0; i < 4; i++)
                #pragma unroll
                for (int j = 0; j < 4; j++)
                    o[i][j] += pp[i] * vv[j];
        }
    }

    // epilogue: normalize, write concat layout [B, S, H*E]
    #pragma unroll
    for (int i = 0; i < 4; i++) {
        float inv = 1.0f / lsum[i];
        int srow = s0 + ty*4 + i;
        float4 v = make_float4(o[i][0]*inv, o[i][1]*inv, o[i][2]*inv, o[i][3]*inv);
        *(float4*)(g_ATT + (size_t)(b*SS + srow)*(NH*HE) + h*HE + tx*4) = v;
    }
}

// ---------------------------------------------------------------------------
// Output projection: ATT[B*S, H*E] @ Wo^T + bo -> out[B*S, OUT]
// Wo is [OUT, H*E]; B-tile loaded along k (contiguous in Wo rows).
// ---------------------------------------------------------------------------
__global__ __launch_bounds__(256) void outproj_kernel(const float* __restrict__ Wo,
                                                      const float* __restrict__ bo,
                                                      float* __restrict__ Y)
{
    __shared__ float As[16][64];
    __shared__ float Bs[16][64];

    const int n0 = blockIdx.x * 64;
    const int m0 = blockIdx.y * 64;
    const int tx = threadIdx.x, ty = threadIdx.y;
    const int tid = ty * 16 + tx;

    const int ar = tid >> 2;
    const int ak = (tid & 3) << 2;
    const int nl = tid >> 2;          // 0..63 : Wo row within tile
    const int k0 = (tid & 3) << 2;    // 0,4,8,12

    float c[4][4] = {};

    for (int kk = 0; kk < NH*HE; kk += 16) {
        float4 av = *(const float4*)(g_ATT + (size_t)(m0 + ar) * (NH*HE) + kk + ak);
        As[ak+0][ar] = av.x; As[ak+1][ar] = av.y;
        As[ak+2][ar] = av.z; As[ak+3][ar] = av.w;
        float4 wv = *(const float4*)(Wo + (size_t)(n0 + nl) * (NH*HE) + kk + k0);
        Bs[k0+0][nl] = wv.x; Bs[k0+1][nl] = wv.y;
        Bs[k0+2][nl] = wv.z; Bs[k0+3][nl] = wv.w;
        __syncthreads();
        #pragma unroll
        for (int k = 0; k < 16; k++) {
            float4 a4 = *(const float4*)(&As[k][ty*4]);
            float4 b4 = *(const float4*)(&Bs[k][tx*4]);
            float aa[4] = {a4.x, a4.y, a4.z, a4.w};
            float bb[4] = {b4.x, b4.y, b4.z, b4.w};
            #pragma unroll
            for (int i = 0; i < 4; i++)
                #pragma unroll
                for (int j = 0; j < 4; j++)
                    c[i][j] += aa[i] * bb[j];
        }
        __syncthreads();
    }

    float4 bias = *(const float4*)(bo + n0 + tx*4);
    float bb[4] = {bias.x, bias.y, bias.z, bias.w};
    #pragma unroll
    for (int i = 0; i < 4; i++) {
        int m = m0 + ty*4 + i;
        float4 v = make_float4(c[i][0]+bb[0], c[i][1]+bb[1], c[i][2]+bb[2], c[i][3]+bb[3]);
        *(float4*)(Y + (size_t)m * DOUT + n0 + tx*4) = v;
    }
}

// ---------------------------------------------------------------------------
extern "C" void kernel_launch(void* const* d_in, const int* in_sizes, int n_in,
                              void* d_out, int out_size)
{
    const float* query = (const float*)d_in[0];
    const float* key   = (const float*)d_in[1];
    const float* value = (const float*)d_in[2];
    const float* Wq    = (const float*)d_in[3];
    const float* Wk    = (const float*)d_in[4];
    const float* Wv    = (const float*)d_in[5];
    const float* Wo    = (const float*)d_in[6];
    const float* bo    = (const float*)d_in[7];
    float* out = (float*)d_out;

    dim3 thr(16, 16);

    proj_kernel<<<dim3(NH, (BB*SS)/64), thr>>>(query, Wq, 0);
    proj_kernel<<<dim3(NH, (BB*SS)/64), thr>>>(key,   Wk, 1);
    proj_kernel<<<dim3(NH, (BB*SS)/64), thr>>>(value, Wv, 2);

    attn_kernel<<<dim3(SS/64, NH, BB), thr>>>();

    outproj_kernel<<<dim3(DOUT/64, (BB*SS)/64), thr>>>(Wo, bo, out);
}

// round 3
// speedup vs baseline: 1.5529x; 1.5529x over previous
#include <cuda_runtime.h>
#include <cuda_bf16.h>
#include <cstdint>

#define BB   8
#define SEQ  1024
#define DQKV 1024
#define NH   16
#define HE   64
#define DOUT 1024
#define MROWS (BB*SEQ)   // 8192

// GEMM tiling
#define TM 128
#define TN 128
#define TK 32
#define SP 40            // padded smem K-stride (bf16 elems) -> conflict-free LDS

// Scratch (allocation-free contract: __device__ globals)
__device__ float g_Q[BB*NH*SEQ*HE];
__device__ float g_K[BB*NH*SEQ*HE];
__device__ float g_V[BB*NH*SEQ*HE];
__device__ float g_ATT[BB*SEQ*NH*HE];

__device__ __forceinline__ void split_bf16(float x, __nv_bfloat16& h, __nv_bfloat16& l) {
    h = __float2bfloat16(x);
    l = __float2bfloat16(x - __bfloat162float(h));
}

__device__ __forceinline__ void mma16816(float* d, const uint32_t* a, const uint32_t* b) {
    asm volatile(
        "mma.sync.aligned.m16n8k16.row.col.f32.bf16.bf16.f32 "
        "{%0,%1,%2,%3}, {%4,%5,%6,%7}, {%8,%9}, {%0,%1,%2,%3};"
        : "+f"(d[0]), "+f"(d[1]), "+f"(d[2]), "+f"(d[3])
        : "r"(a[0]), "r"(a[1]), "r"(a[2]), "r"(a[3]), "r"(b[0]), "r"(b[1]));
}

// ---------------------------------------------------------------------------
// Tensor-core GEMM (mma.sync bf16 split-precision).
// mode 0/1/2: per-head projection  X[8192,1024] @ W[h][1024,64] -> g_Q/K/V [B,H,S,E]
// mode 3:     out-projection       g_ATT[8192,1024] @ Wo^T + bo -> Y [8192,1024]
// CTA: 128x128 tile, 8 warps of 64x32, K-chunk 32.
// ---------------------------------------------------------------------------
__global__ __launch_bounds__(256, 2) void gemm_mma(const float* __restrict__ A,
                                                   const float* __restrict__ Bsrc,
                                                   const float* __restrict__ bias,
                                                   float* __restrict__ outp,
                                                   int mode)
{
    __shared__ __align__(16) __nv_bfloat16 sAhi[TM*SP];
    __shared__ __align__(16) __nv_bfloat16 sAlo[TM*SP];
    __shared__ __align__(16) __nv_bfloat16 sBhi[TN*SP];
    __shared__ __align__(16) __nv_bfloat16 sBlo[TN*SP];

    const int tid  = threadIdx.x;
    const int wid  = tid >> 5;
    const int lane = tid & 31;
    const int m0 = blockIdx.x * TM;
    const int n0 = blockIdx.y * TN;

    const int wm = (wid & 1) * 64;   // warp M offset in tile
    const int wn = (wid >> 1) * 32;  // warp N offset in tile

    const float* Ap = (mode == 3) ? g_ATT : A;

    // fragment base offsets (lane-dependent)
    const int fr = lane >> 2;        // 0..7
    const int fk = (lane & 3) * 2;   // 0,2,4,6

    float acc[4][4][4] = {};         // [mtile][ntile][4]

    for (int kk = 0; kk < DQKV; kk += TK) {
        // ---- stage A tile [128 x 32] ----
        #pragma unroll
        for (int it = 0; it < 4; it++) {
            int idx = tid + it * 256;          // 1024 float4
            int r = idx >> 3, c4 = (idx & 7) * 4;
            float4 v = *(const float4*)(Ap + (size_t)(m0 + r) * DQKV + kk + c4);
            __nv_bfloat16 h0,l0,h1,l1,h2,l2,h3,l3;
            split_bf16(v.x,h0,l0); split_bf16(v.y,h1,l1);
            split_bf16(v.z,h2,l2); split_bf16(v.w,h3,l3);
            __nv_bfloat16* ph = &sAhi[r*SP + c4];
            __nv_bfloat16* pl = &sAlo[r*SP + c4];
            *(__nv_bfloat162*)(ph)   = __nv_bfloat162(h0,h1);
            *(__nv_bfloat162*)(ph+2) = __nv_bfloat162(h2,h3);
            *(__nv_bfloat162*)(pl)   = __nv_bfloat162(l0,l1);
            *(__nv_bfloat162*)(pl+2) = __nv_bfloat162(l2,l3);
        }

        // ---- stage B tile [128 n x 32 k] ----
        if (mode == 3) {
            // Wo rows n0..n0+127, K-contiguous
            #pragma unroll
            for (int it = 0; it < 4; it++) {
                int idx = tid + it * 256;
                int r = idx >> 3, c4 = (idx & 7) * 4;
                float4 v = *(const float4*)(Bsrc + (size_t)(n0 + r) * DQKV + kk + c4);
                __nv_bfloat16 h0,l0,h1,l1,h2,l2,h3,l3;
                split_bf16(v.x,h0,l0); split_bf16(v.y,h1,l1);
                split_bf16(v.z,h2,l2); split_bf16(v.w,h3,l3);
                __nv_bfloat16* ph = &sBhi[r*SP + c4];
                __nv_bfloat16* pl = &sBlo[r*SP + c4];
                *(__nv_bfloat162*)(ph)   = __nv_bfloat162(h0,h1);
                *(__nv_bfloat162*)(ph+2) = __nv_bfloat162(h2,h3);
                *(__nv_bfloat162*)(pl)   = __nv_bfloat162(l0,l1);
                *(__nv_bfloat162*)(pl+2) = __nv_bfloat162(l2,l3);
            }
        } else {
            // B[n][k] = W[h][kk+k][e], n = hl*64 + e  (2 heads per CTA N-tile)
            #pragma unroll
            for (int it = 0; it < 4; it++) {
                int idx = tid + it * 256;      // 1024 float4: hl(2) x k(32) x e4(16)
                int hl = idx >> 9;
                int k  = (idx >> 4) & 31;
                int e4 = (idx & 15) * 4;
                const float* Wh = Bsrc + (size_t)((n0 >> 6) + hl) * DQKV * HE;
                float4 v = *(const float4*)(Wh + (size_t)(kk + k) * HE + e4);
                float vv[4] = {v.x, v.y, v.z, v.w};
                #pragma unroll
                for (int j = 0; j < 4; j++) {
                    __nv_bfloat16 h, l;
                    split_bf16(vv[j], h, l);
                    int n = hl * 64 + e4 + j;
                    sBhi[n*SP + k] = h;
                    sBlo[n*SP + k] = l;
                }
            }
        }
        __syncthreads();

        // ---- MMA: 2 k16 steps, 3 split terms ----
        #pragma unroll
        for (int kt = 0; kt < 2; kt++) {
            const int kb = kt * 16 + fk;
            uint32_t ah[4][4], bh[4][2];
            #pragma unroll
            for (int mt = 0; mt < 4; mt++) {
                const __nv_bfloat16* pa = &sAhi[(wm + mt*16 + fr)*SP + kb];
                ah[mt][0] = *(const uint32_t*)(pa);
                ah[mt][1] = *(const uint32_t*)(pa + 8*SP);
                ah[mt][2] = *(const uint32_t*)(pa + 8);
                ah[mt][3] = *(const uint32_t*)(pa + 8*SP + 8);
            }
            #pragma unroll
            for (int nt = 0; nt < 4; nt++) {
                const __nv_bfloat16* pb = &sBhi[(wn + nt*8 + fr)*SP + kb];
                bh[nt][0] = *(const uint32_t*)(pb);
                bh[nt][1] = *(const uint32_t*)(pb + 8);
            }
            #pragma unroll
            for (int mt = 0; mt < 4; mt++)
                #pragma unroll
                for (int nt = 0; nt < 4; nt++)
                    mma16816(acc[mt][nt], ah[mt], bh[nt]);

            // A_hi x B_lo
            {
                uint32_t bl[4][2];
                #pragma unroll
                for (int nt = 0; nt < 4; nt++) {
                    const __nv_bfloat16* pb = &sBlo[(wn + nt*8 + fr)*SP + kb];
                    bl[nt][0] = *(const uint32_t*)(pb);
                    bl[nt][1] = *(const uint32_t*)(pb + 8);
                }
                #pragma unroll
                for (int mt = 0; mt < 4; mt++)
                    #pragma unroll
                    for (int nt = 0; nt < 4; nt++)
                        mma16816(acc[mt][nt], ah[mt], bl[nt]);
            }

            // A_lo x B_hi
            {
                uint32_t al[4][4];
                #pragma unroll
                for (int mt = 0; mt < 4; mt++) {
                    const __nv_bfloat16* pa = &sAlo[(wm + mt*16 + fr)*SP + kb];
                    al[mt][0] = *(const uint32_t*)(pa);
                    al[mt][1] = *(const uint32_t*)(pa + 8*SP);
                    al[mt][2] = *(const uint32_t*)(pa + 8);
                    al[mt][3] = *(const uint32_t*)(pa + 8*SP + 8);
                }
                #pragma unroll
                for (int mt = 0; mt < 4; mt++)
                    #pragma unroll
                    for (int nt = 0; nt < 4; nt++)
                        mma16816(acc[mt][nt], al[mt], bh[nt]);
            }
        }
        __syncthreads();
    }

    // ---- epilogue ----
    #pragma unroll
    for (int mt = 0; mt < 4; mt++) {
        #pragma unroll
        for (int nt = 0; nt < 4; nt++) {
            int row = m0 + wm + mt*16 + fr;
            int np  = n0 + wn + nt*8 + fk;
            if (mode == 3) {
                float b0 = __ldg(bias + np), b1 = __ldg(bias + np + 1);
                float2 v0 = make_float2(acc[mt][nt][0] + b0, acc[mt][nt][1] + b1);
                float2 v1 = make_float2(acc[mt][nt][2] + b0, acc[mt][nt][3] + b1);
                *(float2*)(outp + (size_t)row * DOUT + np)       = v0;
                *(float2*)(outp + (size_t)(row + 8) * DOUT + np) = v1;
            } else {
                float* dst = (mode == 0 ? g_Q : mode == 1 ? g_K : g_V);
                int h = np >> 6, e = np & 63;
                int b = row >> 10, s = row & 1023;
                float* o0 = dst + ((size_t)((b*NH + h)*SEQ + s)) * HE + e;
                *(float2*)(o0) = make_float2(acc[mt][nt][0], acc[mt][nt][1]);
                int r1 = row + 8;
                int b1i = r1 >> 10, s1 = r1 & 1023;
                float* o1 = dst + ((size_t)((b1i*NH + h)*SEQ + s1)) * HE + e;
                *(float2*)(o1) = make_float2(acc[mt][nt][2], acc[mt][nt][3]);
            }
        }
    }
}

// ---------------------------------------------------------------------------
// Flash-style attention (SIMT, unchanged): one CTA = (64 q rows, head, batch)
// ---------------------------------------------------------------------------
__global__ __launch_bounds__(256) void attn_kernel()
{
    __shared__ float Qs[64*64];
    __shared__ float KP[64*65];
    __shared__ float Vs[64*64];

    const int s0 = blockIdx.x * 64;
    const int h  = blockIdx.y;
    const int b  = blockIdx.z;
    const int tx = threadIdx.x, ty = threadIdx.y;
    const int tid = ty*16 + tx;
    const int lr  = tid >> 4;
    const int lc  = (tid & 15) << 2;

    const float* Qp = g_Q + (size_t)((b*NH + h)*SEQ + s0) * HE;
    const float* Kp = g_K + (size_t)((b*NH + h)*SEQ) * HE;
    const float* Vp = g_V + (size_t)((b*NH + h)*SEQ) * HE;

    const float scale = 0.03125f;

    #pragma unroll
    for (int it = 0; it < 4; it++) {
        int r = lr + it*16;
        float4 v = *(const float4*)(Qp + r*HE + lc);
        Qs[r*64 + lc+0] = v.x * scale;
        Qs[r*64 + lc+1] = v.y * scale;
        Qs[r*64 + lc+2] = v.z * scale;
        Qs[r*64 + lc+3] = v.w * scale;
    }

    float o[4][4] = {};
    float mrow[4] = {-1e30f, -1e30f, -1e30f, -1e30f};
    float lsum[4] = {};

    for (int t = 0; t < SEQ/64; t++) {
        __syncthreads();
        #pragma unroll
        for (int it = 0; it < 4; it++) {
            int r = lr + it*16;
            float4 kv = *(const float4*)(Kp + (t*64 + r)*HE + lc);
            KP[r*65 + lc+0] = kv.x; KP[r*65 + lc+1] = kv.y;
            KP[r*65 + lc+2] = kv.z; KP[r*65 + lc+3] = kv.w;
            float4 vv = *(const float4*)(Vp + (t*64 + r)*HE + lc);
            *(float4*)(&Vs[r*64 + lc]) = vv;
        }
        __syncthreads();

        float sc[4][4] = {};
        #pragma unroll 4
        for (int k = 0; k < 64; k++) {
            float aa[4], bb[4];
            #pragma unroll
            for (int i = 0; i < 4; i++) aa[i] = Qs[(ty*4+i)*64 + k];
            #pragma unroll
            for (int j = 0; j < 4; j++) bb[j] = KP[(tx*4+j)*65 + k];
            #pragma unroll
            for (int i = 0; i < 4; i++)
                #pragma unroll
                for (int j = 0; j < 4; j++)
                    sc[i][j] += aa[i] * bb[j];
        }

        #pragma unroll
        for (int i = 0; i < 4; i++) {
            float tm = fmaxf(fmaxf(sc[i][0], sc[i][1]), fmaxf(sc[i][2], sc[i][3]));
            #pragma unroll
            for (int off = 8; off >= 1; off >>= 1)
                tm = fmaxf(tm, __shfl_xor_sync(0xffffffffu, tm, off));
            float nm   = fmaxf(mrow[i], tm);
            float corr = __expf(mrow[i] - nm);
            float rs = 0.f;
            #pragma unroll
            for (int j = 0; j < 4; j++) {
                sc[i][j] = __expf(sc[i][j] - nm);
                rs += sc[i][j];
            }
            #pragma unroll
            for (int off = 8; off >= 1; off >>= 1)
                rs += __shfl_xor_sync(0xffffffffu, rs, off);
            lsum[i] = lsum[i]*corr + rs;
            mrow[i] = nm;
            #pragma unroll
            for (int j = 0; j < 4; j++) o[i][j] *= corr;
        }

        __syncthreads();
        #pragma unroll
        for (int i = 0; i < 4; i++)
            #pragma unroll
            for (int j = 0; j < 4; j++)
                KP[(ty*4+i)*65 + (tx*4+j)] = sc[i][j];
        __syncthreads();

        #pragma unroll 4
        for (int k = 0; k < 64; k++) {
            float pp[4];
            #pragma unroll
            for (int i = 0; i < 4; i++) pp[i] = KP[(ty*4+i)*65 + k];
            float4 v4 = *(const float4*)(&Vs[k*64 + tx*4]);
            float vv[4] = {v4.x, v4.y, v4.z, v4.w};
            #pragma unroll
            for (int i = 0; i < 4; i++)
                #pragma unroll
                for (int j = 0; j < 4; j++)
                    o[i][j] += pp[i] * vv[j];
        }
    }

    #pragma unroll
    for (int i = 0; i < 4; i++) {
        float inv = 1.0f / lsum[i];
        int srow = s0 + ty*4 + i;
        float4 v = make_float4(o[i][0]*inv, o[i][1]*inv, o[i][2]*inv, o[i][3]*inv);
        *(float4*)(g_ATT + (size_t)(b*SEQ + srow)*(NH*HE) + h*HE + tx*4) = v;
    }
}

// ---------------------------------------------------------------------------
extern "C" void kernel_launch(void* const* d_in, const int* in_sizes, int n_in,
                              void* d_out, int out_size)
{
    const float* query = (const float*)d_in[0];
    const float* key   = (const float*)d_in[1];
    const float* value = (const float*)d_in[2];
    const float* Wq    = (const float*)d_in[3];
    const float* Wk    = (const float*)d_in[4];
    const float* Wv    = (const float*)d_in[5];
    const float* Wo    = (const float*)d_in[6];
    const float* bo    = (const float*)d_in[7];
    float* out = (float*)d_out;

    dim3 gg(MROWS/TM, (NH*HE)/TN);   // (64, 8)

    gemm_mma<<<gg, 256>>>(query, Wq, nullptr, nullptr, 0);
    gemm_mma<<<gg, 256>>>(key,   Wk, nullptr, nullptr, 1);
    gemm_mma<<<gg, 256>>>(value, Wv, nullptr, nullptr, 2);

    attn_kernel<<<dim3(SEQ/64, NH, BB), dim3(16,16)>>>();

    gemm_mma<<<dim3(MROWS/TM, DOUT/TN), 256>>>(nullptr, Wo, bo, out, 3);
}

// round 4
// speedup vs baseline: 1.6226x; 1.0448x over previous
#include <cuda_runtime.h>
#include <cuda_bf16.h>
#include <cstdint>

#define BB   8
#define SEQ  1024
#define DQKV 1024
#define NH   16
#define HE   64
#define DOUT 1024
#define MROWS (BB*SEQ)   // 8192

// GEMM tiling
#define TM 128
#define TN 128
#define TK 32
#define SP 40            // padded smem K-stride (bf16) -> conflict-free LDS

// Scratch (allocation-free contract: __device__ globals)
__device__ __nv_bfloat16 g_Qbf[BB*NH*SEQ*HE];   // [b,h,s,e], scale folded
__device__ __nv_bfloat16 g_Kbf[BB*NH*SEQ*HE];   // [b,h,s,e]
__device__ __nv_bfloat16 g_Vhi[BB*NH*HE*SEQ];   // [b,h,e,s]
__device__ __nv_bfloat16 g_Vlo[BB*NH*HE*SEQ];   // [b,h,e,s]
__device__ float g_ATT[BB*SEQ*NH*HE];           // [b,s,h*e]

__device__ __forceinline__ void split_bf16(float x, __nv_bfloat16& h, __nv_bfloat16& l) {
    h = __float2bfloat16(x);
    l = __float2bfloat16(x - __bfloat162float(h));
}

__device__ __forceinline__ void mma16816(float* d, const uint32_t* a, const uint32_t* b) {
    asm volatile(
        "mma.sync.aligned.m16n8k16.row.col.f32.bf16.bf16.f32 "
        "{%0,%1,%2,%3}, {%4,%5,%6,%7}, {%8,%9}, {%0,%1,%2,%3};"
        : "+f"(d[0]), "+f"(d[1]), "+f"(d[2]), "+f"(d[3])
        : "r"(a[0]), "r"(a[1]), "r"(a[2]), "r"(a[3]), "r"(b[0]), "r"(b[1]));
}

__device__ __forceinline__ uint32_t pack_bf2(__nv_bfloat16 lo, __nv_bfloat16 hi) {
    __nv_bfloat162 t(lo, hi);
    return *(uint32_t*)&t;
}

// ---------------------------------------------------------------------------
// Tensor-core GEMM (3-term split-bf16), templated epilogue.
// MODE 0: X@Wq -> g_Qbf (bf16, scale folded)   [b,h,s,e]
// MODE 1: X@Wk -> g_Kbf (bf16)                 [b,h,s,e]
// MODE 2: X@Wv -> g_Vhi/g_Vlo (bf16 split)     [b,h,e,s]
// MODE 3: g_ATT@Wo^T + bo -> out (fp32)
// ---------------------------------------------------------------------------
template<int MODE>
__global__ __launch_bounds__(256, 2) void gemm_mma(const float* __restrict__ A,
                                                   const float* __restrict__ Bsrc,
                                                   const float* __restrict__ bias,
                                                   float* __restrict__ outp)
{
    __shared__ __align__(16) __nv_bfloat16 sAhi[TM*SP];
    __shared__ __align__(16) __nv_bfloat16 sAlo[TM*SP];
    __shared__ __align__(16) __nv_bfloat16 sBhi[TN*SP];
    __shared__ __align__(16) __nv_bfloat16 sBlo[TN*SP];

    const int tid  = threadIdx.x;
    const int wid  = tid >> 5;
    const int lane = tid & 31;
    const int m0 = blockIdx.x * TM;
    const int n0 = blockIdx.y * TN;

    const int wm = (wid & 1) * 64;
    const int wn = (wid >> 1) * 32;

    const float* Ap = (MODE == 3) ? g_ATT : A;

    const int fr = lane >> 2;
    const int fk = (lane & 3) * 2;

    float acc[4][4][4] = {};

    for (int kk = 0; kk < DQKV; kk += TK) {
        #pragma unroll
        for (int it = 0; it < 4; it++) {
            int idx = tid + it * 256;
            int r = idx >> 3, c4 = (idx & 7) * 4;
            float4 v = *(const float4*)(Ap + (size_t)(m0 + r) * DQKV + kk + c4);
            __nv_bfloat16 h0,l0,h1,l1,h2,l2,h3,l3;
            split_bf16(v.x,h0,l0); split_bf16(v.y,h1,l1);
            split_bf16(v.z,h2,l2); split_bf16(v.w,h3,l3);
            __nv_bfloat16* ph = &sAhi[r*SP + c4];
            __nv_bfloat16* pl = &sAlo[r*SP + c4];
            *(__nv_bfloat162*)(ph)   = __nv_bfloat162(h0,h1);
            *(__nv_bfloat162*)(ph+2) = __nv_bfloat162(h2,h3);
            *(__nv_bfloat162*)(pl)   = __nv_bfloat162(l0,l1);
            *(__nv_bfloat162*)(pl+2) = __nv_bfloat162(l2,l3);
        }

        if (MODE == 3) {
            #pragma unroll
            for (int it = 0; it < 4; it++) {
                int idx = tid + it * 256;
                int r = idx >> 3, c4 = (idx & 7) * 4;
                float4 v = *(const float4*)(Bsrc + (size_t)(n0 + r) * DQKV + kk + c4);
                __nv_bfloat16 h0,l0,h1,l1,h2,l2,h3,l3;
                split_bf16(v.x,h0,l0); split_bf16(v.y,h1,l1);
                split_bf16(v.z,h2,l2); split_bf16(v.w,h3,l3);
                __nv_bfloat16* ph = &sBhi[r*SP + c4];
                __nv_bfloat16* pl = &sBlo[r*SP + c4];
                *(__nv_bfloat162*)(ph)   = __nv_bfloat162(h0,h1);
                *(__nv_bfloat162*)(ph+2) = __nv_bfloat162(h2,h3);
                *(__nv_bfloat162*)(pl)   = __nv_bfloat162(l0,l1);
                *(__nv_bfloat162*)(pl+2) = __nv_bfloat162(l2,l3);
            }
        } else {
            #pragma unroll
            for (int it = 0; it < 4; it++) {
                int idx = tid + it * 256;
                int hl = idx >> 9;
                int k  = (idx >> 4) & 31;
                int e4 = (idx & 15) * 4;
                const float* Wh = Bsrc + (size_t)((n0 >> 6) + hl) * DQKV * HE;
                float4 v = *(const float4*)(Wh + (size_t)(kk + k) * HE + e4);
                float vv[4] = {v.x, v.y, v.z, v.w};
                #pragma unroll
                for (int j = 0; j < 4; j++) {
                    __nv_bfloat16 h, l;
                    split_bf16(vv[j], h, l);
                    int n = hl * 64 + e4 + j;
                    sBhi[n*SP + k] = h;
                    sBlo[n*SP + k] = l;
                }
            }
        }
        __syncthreads();

        #pragma unroll
        for (int kt = 0; kt < 2; kt++) {
            const int kb = kt * 16 + fk;
            uint32_t ah[4][4], bh[4][2];
            #pragma unroll
            for (int mt = 0; mt < 4; mt++) {
                const __nv_bfloat16* pa = &sAhi[(wm + mt*16 + fr)*SP + kb];
                ah[mt][0] = *(const uint32_t*)(pa);
                ah[mt][1] = *(const uint32_t*)(pa + 8*SP);
                ah[mt][2] = *(const uint32_t*)(pa + 8);
                ah[mt][3] = *(const uint32_t*)(pa + 8*SP + 8);
            }
            #pragma unroll
            for (int nt = 0; nt < 4; nt++) {
                const __nv_bfloat16* pb = &sBhi[(wn + nt*8 + fr)*SP + kb];
                bh[nt][0] = *(const uint32_t*)(pb);
                bh[nt][1] = *(const uint32_t*)(pb + 8);
            }
            #pragma unroll
            for (int mt = 0; mt < 4; mt++)
                #pragma unroll
                for (int nt = 0; nt < 4; nt++)
                    mma16816(acc[mt][nt], ah[mt], bh[nt]);
            {
                uint32_t bl[4][2];
                #pragma unroll
                for (int nt = 0; nt < 4; nt++) {
                    const __nv_bfloat16* pb = &sBlo[(wn + nt*8 + fr)*SP + kb];
                    bl[nt][0] = *(const uint32_t*)(pb);
                    bl[nt][1] = *(const uint32_t*)(pb + 8);
                }
                #pragma unroll
                for (int mt = 0; mt < 4; mt++)
                    #pragma unroll
                    for (int nt = 0; nt < 4; nt++)
                        mma16816(acc[mt][nt], ah[mt], bl[nt]);
            }
            {
                uint32_t al[4][4];
                #pragma unroll
                for (int mt = 0; mt < 4; mt++) {
                    const __nv_bfloat16* pa = &sAlo[(wm + mt*16 + fr)*SP + kb];
                    al[mt][0] = *(const uint32_t*)(pa);
                    al[mt][1] = *(const uint32_t*)(pa + 8*SP);
                    al[mt][2] = *(const uint32_t*)(pa + 8);
                    al[mt][3] = *(const uint32_t*)(pa + 8*SP + 8);
                }
                #pragma unroll
                for (int mt = 0; mt < 4; mt++)
                    #pragma unroll
                    for (int nt = 0; nt < 4; nt++)
                        mma16816(acc[mt][nt], al[mt], bh[nt]);
            }
        }
        __syncthreads();
    }

    // ---- epilogue ----
    const float qscale = 0.03125f;   // 1/sqrt(1024)
    #pragma unroll
    for (int mt = 0; mt < 4; mt++) {
        #pragma unroll
        for (int nt = 0; nt < 4; nt++) {
            int row = m0 + wm + mt*16 + fr;
            int np  = n0 + wn + nt*8 + fk;
            if (MODE == 3) {
                float b0 = __ldg(bias + np), b1 = __ldg(bias + np + 1);
                *(float2*)(outp + (size_t)row * DOUT + np) =
                    make_float2(acc[mt][nt][0] + b0, acc[mt][nt][1] + b1);
                *(float2*)(outp + (size_t)(row + 8) * DOUT + np) =
                    make_float2(acc[mt][nt][2] + b0, acc[mt][nt][3] + b1);
            } else {
                int h = np >> 6, e = np & 63;
                int b = row >> 10, s = row & 1023;
                int r1 = row + 8;
                int b1i = r1 >> 10, s1 = r1 & 1023;
                if (MODE == 0 || MODE == 1) {
                    __nv_bfloat16* dst = (MODE == 0) ? g_Qbf : g_Kbf;
                    float f = (MODE == 0) ? qscale : 1.0f;
                    *(__nv_bfloat162*)(dst + ((size_t)((b*NH + h)*SEQ + s))*HE + e) =
                        __nv_bfloat162(__float2bfloat16(acc[mt][nt][0]*f),
                                       __float2bfloat16(acc[mt][nt][1]*f));
                    *(__nv_bfloat162*)(dst + ((size_t)((b1i*NH + h)*SEQ + s1))*HE + e) =
                        __nv_bfloat162(__float2bfloat16(acc[mt][nt][2]*f),
                                       __float2bfloat16(acc[mt][nt][3]*f));
                } else {  // MODE 2: V split, transposed [b,h,e,s]
                    #pragma unroll
                    for (int j = 0; j < 2; j++) {
                        __nv_bfloat16 vh, vl;
                        split_bf16(acc[mt][nt][j], vh, vl);
                        size_t o = ((size_t)((b*NH + h)*HE + e + j))*SEQ + s;
                        g_Vhi[o] = vh; g_Vlo[o] = vl;
                        split_bf16(acc[mt][nt][2+j], vh, vl);
                        size_t o1 = ((size_t)((b1i*NH + h)*HE + e + j))*SEQ + s1;
                        g_Vhi[o1] = vh; g_Vlo[o1] = vl;
                    }
                }
            }
        }
    }
}

// ---------------------------------------------------------------------------
// Tensor-core flash attention.
// CTA: 128 q rows of one (b,h). 8 warps x 16 rows. KV tile = 128.
// Scores: bf16 1-term. PV: 3-term split. Online softmax in fragments.
// ---------------------------------------------------------------------------
#define SKQ 72    // sK row stride (bf16)
#define SVP 136   // sV row stride (bf16)
#define SM_K   0
#define SM_VH  (128*SKQ*2)              // 18432
#define SM_VL  (SM_VH + 64*SVP*2)       // 35840
#define SM_ATT (SM_VL + 64*SVP*2)       // 53248 total

__global__ __launch_bounds__(256) void attn_mma()
{
    extern __shared__ char sm[];
    __nv_bfloat16* sK  = (__nv_bfloat16*)(sm + SM_K);
    __nv_bfloat16* sVh = (__nv_bfloat16*)(sm + SM_VH);
    __nv_bfloat16* sVl = (__nv_bfloat16*)(sm + SM_VL);

    const int q0 = blockIdx.x * 128;
    const int h  = blockIdx.y;
    const int b  = blockIdx.z;
    const int tid  = threadIdx.x;
    const int wid  = tid >> 5;
    const int lane = tid & 31;
    const int fr = lane >> 2;
    const int fk = (lane & 3) * 2;
    const int wr = wid * 16;

    const size_t bh = (size_t)(b*NH + h);
    const __nv_bfloat16* gQ = g_Qbf + bh*SEQ*HE;
    const __nv_bfloat16* gK = g_Kbf + bh*SEQ*HE;
    const __nv_bfloat16* gVh = g_Vhi + bh*HE*SEQ;
    const __nv_bfloat16* gVl = g_Vlo + bh*HE*SEQ;

    // ---- stage Q into sK region, extract a-frags ----
    #pragma unroll
    for (int it = 0; it < 4; it++) {
        int idx = tid + it * 256;            // 1024 uint4
        int r = idx >> 3, c8 = (idx & 7) * 8;
        *(uint4*)&sK[r*SKQ + c8] = *(const uint4*)(gQ + (size_t)(q0 + r)*HE + c8);
    }
    __syncthreads();
    uint32_t qa[4][4];
    #pragma unroll
    for (int kt = 0; kt < 4; kt++) {
        const __nv_bfloat16* pa = &sK[(wr + fr)*SKQ + kt*16 + fk];
        qa[kt][0] = *(const uint32_t*)(pa);
        qa[kt][1] = *(const uint32_t*)(pa + 8*SKQ);
        qa[kt][2] = *(const uint32_t*)(pa + 8);
        qa[kt][3] = *(const uint32_t*)(pa + 8*SKQ + 8);
    }
    __syncthreads();

    float oacc[8][4] = {};
    float mrow[2] = {-1e30f, -1e30f};
    float lrow[2] = {0.f, 0.f};

    for (int t = 0; t < SEQ/128; t++) {
        // ---- stage K [128 kv][64 e] and V [64 e][128 kv] hi/lo ----
        #pragma unroll
        for (int it = 0; it < 4; it++) {
            int idx = tid + it * 256;
            int r = idx >> 3, c8 = (idx & 7) * 8;
            *(uint4*)&sK[r*SKQ + c8] = *(const uint4*)(gK + (size_t)(t*128 + r)*HE + c8);
        }
        #pragma unroll
        for (int it = 0; it < 4; it++) {
            int idx = tid + it * 256;
            int e = idx >> 4, c8 = (idx & 15) * 8;
            *(uint4*)&sVh[e*SVP + c8] = *(const uint4*)(gVh + (size_t)e*SEQ + t*128 + c8);
            *(uint4*)&sVl[e*SVP + c8] = *(const uint4*)(gVl + (size_t)e*SEQ + t*128 + c8);
        }
        __syncthreads();

        // ---- scores: 16 n-tiles x 4 k-steps ----
        float sc[16][4];
        #pragma unroll
        for (int nt = 0; nt < 16; nt++) {
            sc[nt][0] = sc[nt][1] = sc[nt][2] = sc[nt][3] = 0.f;
            #pragma unroll
            for (int kt = 0; kt < 4; kt++) {
                const __nv_bfloat16* pb = &sK[(nt*8 + fr)*SKQ + kt*16 + fk];
                uint32_t bfr[2];
                bfr[0] = *(const uint32_t*)(pb);
                bfr[1] = *(const uint32_t*)(pb + 8);
                mma16816(sc[nt], qa[kt], bfr);
            }
        }

        // ---- online softmax (rows fr, fr+8; quad shfl) ----
        float tm0 = -1e30f, tm1 = -1e30f;
        #pragma unroll
        for (int nt = 0; nt < 16; nt++) {
            tm0 = fmaxf(tm0, fmaxf(sc[nt][0], sc[nt][1]));
            tm1 = fmaxf(tm1, fmaxf(sc[nt][2], sc[nt][3]));
        }
        #pragma unroll
        for (int off = 1; off <= 2; off <<= 1) {
            tm0 = fmaxf(tm0, __shfl_xor_sync(0xffffffffu, tm0, off));
            tm1 = fmaxf(tm1, __shfl_xor_sync(0xffffffffu, tm1, off));
        }
        float nm0 = fmaxf(mrow[0], tm0), nm1 = fmaxf(mrow[1], tm1);
        float corr0 = __expf(mrow[0] - nm0), corr1 = __expf(mrow[1] - nm1);
        float rs0 = 0.f, rs1 = 0.f;
        #pragma unroll
        for (int nt = 0; nt < 16; nt++) {
            sc[nt][0] = __expf(sc[nt][0] - nm0);
            sc[nt][1] = __expf(sc[nt][1] - nm0);
            sc[nt][2] = __expf(sc[nt][2] - nm1);
            sc[nt][3] = __expf(sc[nt][3] - nm1);
            rs0 += sc[nt][0] + sc[nt][1];
            rs1 += sc[nt][2] + sc[nt][3];
        }
        #pragma unroll
        for (int off = 1; off <= 2; off <<= 1) {
            rs0 += __shfl_xor_sync(0xffffffffu, rs0, off);
            rs1 += __shfl_xor_sync(0xffffffffu, rs1, off);
        }
        lrow[0] = lrow[0]*corr0 + rs0;
        lrow[1] = lrow[1]*corr1 + rs1;
        mrow[0] = nm0; mrow[1] = nm1;
        #pragma unroll
        for (int nt = 0; nt < 8; nt++) {
            oacc[nt][0] *= corr0; oacc[nt][1] *= corr0;
            oacc[nt][2] *= corr1; oacc[nt][3] *= corr1;
        }

        // ---- PV: O += P @ V, 3-term split ----
        #pragma unroll
        for (int kt2 = 0; kt2 < 8; kt2++) {
            uint32_t phi[4], plo[4];
            {
                __nv_bfloat16 h0,l0,h1,l1;
                split_bf16(sc[2*kt2][0], h0, l0); split_bf16(sc[2*kt2][1], h1, l1);
                phi[0] = pack_bf2(h0,h1); plo[0] = pack_bf2(l0,l1);
                split_bf16(sc[2*kt2][2], h0, l0); split_bf16(sc[2*kt2][3], h1, l1);
                phi[1] = pack_bf2(h0,h1); plo[1] = pack_bf2(l0,l1);
                split_bf16(sc[2*kt2+1][0], h0, l0); split_bf16(sc[2*kt2+1][1], h1, l1);
                phi[2] = pack_bf2(h0,h1); plo[2] = pack_bf2(l0,l1);
                split_bf16(sc[2*kt2+1][2], h0, l0); split_bf16(sc[2*kt2+1][3], h1, l1);
                phi[3] = pack_bf2(h0,h1); plo[3] = pack_bf2(l0,l1);
            }
            #pragma unroll
            for (int nt2 = 0; nt2 < 8; nt2++) {
                const __nv_bfloat16* pbh = &sVh[(nt2*8 + fr)*SVP + kt2*16 + fk];
                const __nv_bfloat16* pbl = &sVl[(nt2*8 + fr)*SVP + kt2*16 + fk];
                uint32_t bh[2], bl[2];
                bh[0] = *(const uint32_t*)(pbh); bh[1] = *(const uint32_t*)(pbh + 8);
                bl[0] = *(const uint32_t*)(pbl); bl[1] = *(const uint32_t*)(pbl + 8);
                mma16816(oacc[nt2], phi, bh);
                mma16816(oacc[nt2], phi, bl);
                mma16816(oacc[nt2], plo, bh);
            }
        }
        __syncthreads();
    }

    // ---- epilogue: normalize, write g_ATT [b,s,h*e] fp32 ----
    float inv0 = 1.0f / lrow[0], inv1 = 1.0f / lrow[1];
    int row0 = q0 + wr + fr;
    #pragma unroll
    for (int nt2 = 0; nt2 < 8; nt2++) {
        int e = nt2*8 + fk;
        *(float2*)(g_ATT + ((size_t)(b*SEQ + row0))*(NH*HE) + h*HE + e) =
            make_float2(oacc[nt2][0]*inv0, oacc[nt2][1]*inv0);
        *(float2*)(g_ATT + ((size_t)(b*SEQ + row0 + 8))*(NH*HE) + h*HE + e) =
            make_float2(oacc[nt2][2]*inv1, oacc[nt2][3]*inv1);
    }
}

// ---------------------------------------------------------------------------
extern "C" void kernel_launch(void* const* d_in, const int* in_sizes, int n_in,
                              void* d_out, int out_size)
{
    const float* query = (const float*)d_in[0];
    const float* key   = (const float*)d_in[1];
    const float* value = (const float*)d_in[2];
    const float* Wq    = (const float*)d_in[3];
    const float* Wk    = (const float*)d_in[4];
    const float* Wv    = (const float*)d_in[5];
    const float* Wo    = (const float*)d_in[6];
    const float* bo    = (const float*)d_in[7];
    float* out = (float*)d_out;

    static bool attr_set = false;
    if (!attr_set) {
        cudaFuncSetAttribute(attn_mma, cudaFuncAttributeMaxDynamicSharedMemorySize, SM_ATT);
        attr_set = true;
    }

    dim3 gg(MROWS/TM, (NH*HE)/TN);   // (64, 8)

    gemm_mma<0><<<gg, 256>>>(query, Wq, nullptr, nullptr);
    gemm_mma<1><<<gg, 256>>>(key,   Wk, nullptr, nullptr);
    gemm_mma<2><<<gg, 256>>>(value, Wv, nullptr, nullptr);

    attn_mma<<<dim3(SEQ/128, NH, BB), 256, SM_ATT>>>();

    gemm_mma<3><<<dim3(MROWS/TM, DOUT/TN), 256>>>(nullptr, Wo, bo, out);
}

// round 5
// speedup vs baseline: 2.1521x; 1.3264x over previous
#include <cuda_runtime.h>
#include <cuda_bf16.h>
#include <cstdint>

#define BB   8
#define SEQ  1024
#define DQKV 1024
#define NH   16
#define HE   64
#define DOUT 1024
#define MROWS (BB*SEQ)   // 8192

// GEMM tiling
#define TM 128
#define TN 128
#define TK 32
#define SP 40            // padded smem K-stride (bf16) -> conflict-free LDS
#define NCH (DQKV/TK)    // 32

// Scratch (allocation-free contract: __device__ globals)
__device__ __nv_bfloat16 g_Qbf[BB*NH*SEQ*HE];   // [b,h,s,e], scale folded
__device__ __nv_bfloat16 g_Kbf[BB*NH*SEQ*HE];   // [b,h,s,e]
__device__ __nv_bfloat16 g_Vhi[BB*NH*SEQ*HE];   // [b,h,s,e]  (coalesced now)
__device__ __nv_bfloat16 g_Vlo[BB*NH*SEQ*HE];   // [b,h,s,e]
__device__ float g_ATT[BB*SEQ*NH*HE];           // [b,s,h*e]

__device__ __forceinline__ void split_bf16(float x, __nv_bfloat16& h, __nv_bfloat16& l) {
    h = __float2bfloat16(x);
    l = __float2bfloat16(x - __bfloat162float(h));
}

__device__ __forceinline__ void mma16816(float* d, const uint32_t* a, const uint32_t* b) {
    asm volatile(
        "mma.sync.aligned.m16n8k16.row.col.f32.bf16.bf16.f32 "
        "{%0,%1,%2,%3}, {%4,%5,%6,%7}, {%8,%9}, {%0,%1,%2,%3};"
        : "+f"(d[0]), "+f"(d[1]), "+f"(d[2]), "+f"(d[3])
        : "r"(a[0]), "r"(a[1]), "r"(a[2]), "r"(a[3]), "r"(b[0]), "r"(b[1]));
}

__device__ __forceinline__ uint32_t pack_bf2(__nv_bfloat16 lo, __nv_bfloat16 hi) {
    __nv_bfloat162 t(lo, hi);
    return *(uint32_t*)&t;
}

// ---------------------------------------------------------------------------
// Tensor-core GEMM (3-term split-bf16) with register prefetch.
// MODE 0: X@Wq -> g_Qbf (bf16, scale folded)
// MODE 1: X@Wk -> g_Kbf
// MODE 2: X@Wv -> g_Vhi/g_Vlo (bf16 split, [b,h,s,e] coalesced)
// MODE 3: g_ATT@Wo^T + bo -> out (fp32)
// ---------------------------------------------------------------------------
template<int MODE>
__global__ __launch_bounds__(256, 2) void gemm_mma(const float* __restrict__ A,
                                                   const float* __restrict__ Bsrc,
                                                   const float* __restrict__ bias,
                                                   float* __restrict__ outp)
{
    __shared__ __align__(16) __nv_bfloat16 sAhi[TM*SP];
    __shared__ __align__(16) __nv_bfloat16 sAlo[TM*SP];
    __shared__ __align__(16) __nv_bfloat16 sBhi[TN*SP];
    __shared__ __align__(16) __nv_bfloat16 sBlo[TN*SP];

    const int tid  = threadIdx.x;
    const int wid  = tid >> 5;
    const int lane = tid & 31;
    const int m0 = blockIdx.x * TM;
    const int n0 = blockIdx.y * TN;

    const int wm = (wid & 1) * 64;
    const int wn = (wid >> 1) * 32;

    const float* Ap = (MODE == 3) ? g_ATT : A;

    const int fr = lane >> 2;
    const int fk = (lane & 3) * 2;

    float acc[4][4][4] = {};
    float4 ar[4], br[4];

    // ---- prefetch chunk 0 ----
    #pragma unroll
    for (int it = 0; it < 4; it++) {
        int idx = tid + it * 256;
        int r = idx >> 3, c4 = (idx & 7) * 4;
        ar[it] = *(const float4*)(Ap + (size_t)(m0 + r) * DQKV + c4);
    }
    if (MODE == 3) {
        #pragma unroll
        for (int it = 0; it < 4; it++) {
            int idx = tid + it * 256;
            int r = idx >> 3, c4 = (idx & 7) * 4;
            br[it] = *(const float4*)(Bsrc + (size_t)(n0 + r) * DQKV + c4);
        }
    } else {
        #pragma unroll
        for (int it = 0; it < 4; it++) {
            int idx = tid + it * 256;
            int hl = idx >> 9, k = (idx >> 4) & 31, e4 = (idx & 15) * 4;
            const float* Wh = Bsrc + (size_t)((n0 >> 6) + hl) * DQKV * HE;
            br[it] = *(const float4*)(Wh + (size_t)k * HE + e4);
        }
    }

    for (int ch = 0; ch < NCH; ch++) {
        // ---- convert + store current regs -> smem ----
        #pragma unroll
        for (int it = 0; it < 4; it++) {
            int idx = tid + it * 256;
            int r = idx >> 3, c4 = (idx & 7) * 4;
            __nv_bfloat16 h0,l0,h1,l1,h2,l2,h3,l3;
            split_bf16(ar[it].x,h0,l0); split_bf16(ar[it].y,h1,l1);
            split_bf16(ar[it].z,h2,l2); split_bf16(ar[it].w,h3,l3);
            __nv_bfloat16* ph = &sAhi[r*SP + c4];
            __nv_bfloat16* pl = &sAlo[r*SP + c4];
            *(__nv_bfloat162*)(ph)   = __nv_bfloat162(h0,h1);
            *(__nv_bfloat162*)(ph+2) = __nv_bfloat162(h2,h3);
            *(__nv_bfloat162*)(pl)   = __nv_bfloat162(l0,l1);
            *(__nv_bfloat162*)(pl+2) = __nv_bfloat162(l2,l3);
        }
        if (MODE == 3) {
            #pragma unroll
            for (int it = 0; it < 4; it++) {
                int idx = tid + it * 256;
                int r = idx >> 3, c4 = (idx & 7) * 4;
                __nv_bfloat16 h0,l0,h1,l1,h2,l2,h3,l3;
                split_bf16(br[it].x,h0,l0); split_bf16(br[it].y,h1,l1);
                split_bf16(br[it].z,h2,l2); split_bf16(br[it].w,h3,l3);
                __nv_bfloat16* ph = &sBhi[r*SP + c4];
                __nv_bfloat16* pl = &sBlo[r*SP + c4];
                *(__nv_bfloat162*)(ph)   = __nv_bfloat162(h0,h1);
                *(__nv_bfloat162*)(ph+2) = __nv_bfloat162(h2,h3);
                *(__nv_bfloat162*)(pl)   = __nv_bfloat162(l0,l1);
                *(__nv_bfloat162*)(pl+2) = __nv_bfloat162(l2,l3);
            }
        } else {
            #pragma unroll
            for (int it = 0; it < 4; it++) {
                int idx = tid + it * 256;
                int hl = idx >> 9, k = (idx >> 4) & 31, e4 = (idx & 15) * 4;
                float vv[4] = {br[it].x, br[it].y, br[it].z, br[it].w};
                #pragma unroll
                for (int j = 0; j < 4; j++) {
                    __nv_bfloat16 h, l;
                    split_bf16(vv[j], h, l);
                    int n = hl * 64 + e4 + j;
                    sBhi[n*SP + k] = h;
                    sBlo[n*SP + k] = l;
                }
            }
        }
        __syncthreads();

        // ---- prefetch next chunk (hidden under MMAs) ----
        if (ch + 1 < NCH) {
            const int kk = (ch + 1) * TK;
            #pragma unroll
            for (int it = 0; it < 4; it++) {
                int idx = tid + it * 256;
                int r = idx >> 3, c4 = (idx & 7) * 4;
                ar[it] = *(const float4*)(Ap + (size_t)(m0 + r) * DQKV + kk + c4);
            }
            if (MODE == 3) {
                #pragma unroll
                for (int it = 0; it < 4; it++) {
                    int idx = tid + it * 256;
                    int r = idx >> 3, c4 = (idx & 7) * 4;
                    br[it] = *(const float4*)(Bsrc + (size_t)(n0 + r) * DQKV + kk + c4);
                }
            } else {
                #pragma unroll
                for (int it = 0; it < 4; it++) {
                    int idx = tid + it * 256;
                    int hl = idx >> 9, k = (idx >> 4) & 31, e4 = (idx & 15) * 4;
                    const float* Wh = Bsrc + (size_t)((n0 >> 6) + hl) * DQKV * HE;
                    br[it] = *(const float4*)(Wh + (size_t)(kk + k) * HE + e4);
                }
            }
        }

        // ---- MMAs ----
        #pragma unroll
        for (int kt = 0; kt < 2; kt++) {
            const int kb = kt * 16 + fk;
            uint32_t ah[4][4], bh[4][2];
            #pragma unroll
            for (int mt = 0; mt < 4; mt++) {
                const __nv_bfloat16* pa = &sAhi[(wm + mt*16 + fr)*SP + kb];
                ah[mt][0] = *(const uint32_t*)(pa);
                ah[mt][1] = *(const uint32_t*)(pa + 8*SP);
                ah[mt][2] = *(const uint32_t*)(pa + 8);
                ah[mt][3] = *(const uint32_t*)(pa + 8*SP + 8);
            }
            #pragma unroll
            for (int nt = 0; nt < 4; nt++) {
                const __nv_bfloat16* pb = &sBhi[(wn + nt*8 + fr)*SP + kb];
                bh[nt][0] = *(const uint32_t*)(pb);
                bh[nt][1] = *(const uint32_t*)(pb + 8);
            }
            #pragma unroll
            for (int mt = 0; mt < 4; mt++)
                #pragma unroll
                for (int nt = 0; nt < 4; nt++)
                    mma16816(acc[mt][nt], ah[mt], bh[nt]);
            {
                uint32_t bl[4][2];
                #pragma unroll
                for (int nt = 0; nt < 4; nt++) {
                    const __nv_bfloat16* pb = &sBlo[(wn + nt*8 + fr)*SP + kb];
                    bl[nt][0] = *(const uint32_t*)(pb);
                    bl[nt][1] = *(const uint32_t*)(pb + 8);
                }
                #pragma unroll
                for (int mt = 0; mt < 4; mt++)
                    #pragma unroll
                    for (int nt = 0; nt < 4; nt++)
                        mma16816(acc[mt][nt], ah[mt], bl[nt]);
            }
            {
                uint32_t al[4][4];
                #pragma unroll
                for (int mt = 0; mt < 4; mt++) {
                    const __nv_bfloat16* pa = &sAlo[(wm + mt*16 + fr)*SP + kb];
                    al[mt][0] = *(const uint32_t*)(pa);
                    al[mt][1] = *(const uint32_t*)(pa + 8*SP);
                    al[mt][2] = *(const uint32_t*)(pa + 8);
                    al[mt][3] = *(const uint32_t*)(pa + 8*SP + 8);
                }
                #pragma unroll
                for (int mt = 0; mt < 4; mt++)
                    #pragma unroll
                    for (int nt = 0; nt < 4; nt++)
                        mma16816(acc[mt][nt], al[mt], bh[nt]);
            }
        }
        __syncthreads();
    }

    // ---- epilogue ----
    const float qscale = 0.03125f;   // 1/sqrt(1024)
    #pragma unroll
    for (int mt = 0; mt < 4; mt++) {
        #pragma unroll
        for (int nt = 0; nt < 4; nt++) {
            int row = m0 + wm + mt*16 + fr;
            int np  = n0 + wn + nt*8 + fk;
            if (MODE == 3) {
                float b0 = __ldg(bias + np), b1 = __ldg(bias + np + 1);
                *(float2*)(outp + (size_t)row * DOUT + np) =
                    make_float2(acc[mt][nt][0] + b0, acc[mt][nt][1] + b1);
                *(float2*)(outp + (size_t)(row + 8) * DOUT + np) =
                    make_float2(acc[mt][nt][2] + b0, acc[mt][nt][3] + b1);
            } else {
                int h = np >> 6, e = np & 63;
                int b = row >> 10, s = row & 1023;
                int r1 = row + 8;
                int b1i = r1 >> 10, s1 = r1 & 1023;
                if (MODE == 0 || MODE == 1) {
                    __nv_bfloat16* dst = (MODE == 0) ? g_Qbf : g_Kbf;
                    float f = (MODE == 0) ? qscale : 1.0f;
                    *(__nv_bfloat162*)(dst + ((size_t)((b*NH + h)*SEQ + s))*HE + e) =
                        __nv_bfloat162(__float2bfloat16(acc[mt][nt][0]*f),
                                       __float2bfloat16(acc[mt][nt][1]*f));
                    *(__nv_bfloat162*)(dst + ((size_t)((b1i*NH + h)*SEQ + s1))*HE + e) =
                        __nv_bfloat162(__float2bfloat16(acc[mt][nt][2]*f),
                                       __float2bfloat16(acc[mt][nt][3]*f));
                } else {  // MODE 2: V split hi/lo, coalesced [b,h,s,e]
                    __nv_bfloat16 h0,l0,h1,l1;
                    split_bf16(acc[mt][nt][0], h0, l0);
                    split_bf16(acc[mt][nt][1], h1, l1);
                    size_t base = ((size_t)((b*NH + h)*SEQ + s))*HE + e;
                    *(__nv_bfloat162*)(g_Vhi + base) = __nv_bfloat162(h0, h1);
                    *(__nv_bfloat162*)(g_Vlo + base) = __nv_bfloat162(l0, l1);
                    split_bf16(acc[mt][nt][2], h0, l0);
                    split_bf16(acc[mt][nt][3], h1, l1);
                    size_t base1 = ((size_t)((b1i*NH + h)*SEQ + s1))*HE + e;
                    *(__nv_bfloat162*)(g_Vhi + base1) = __nv_bfloat162(h0, h1);
                    *(__nv_bfloat162*)(g_Vlo + base1) = __nv_bfloat162(l0, l1);
                }
            }
        }
    }
}

// ---------------------------------------------------------------------------
// Tensor-core flash attention.
// CTA: 64 q rows of one (b,h), 128 threads (4 warps x 16 rows). KV tile = 128.
// V transposed [e][s] during smem staging (global layout is coalesced [s][e]).
// ---------------------------------------------------------------------------
#define SKQ 72    // sK row stride (bf16)
#define SVP 136   // sV row stride (bf16)
#define SM_K   0
#define SM_VH  (128*SKQ*2)              // 18432
#define SM_VL  (SM_VH + 64*SVP*2)       // 35840
#define SM_ATT (SM_VL + 64*SVP*2)       // 53248 total

__global__ __launch_bounds__(128) void attn_mma()
{
    extern __shared__ char sm[];
    __nv_bfloat16* sK  = (__nv_bfloat16*)(sm + SM_K);
    __nv_bfloat16* sVh = (__nv_bfloat16*)(sm + SM_VH);
    __nv_bfloat16* sVl = (__nv_bfloat16*)(sm + SM_VL);

    const int q0 = blockIdx.x * 64;
    const int h  = blockIdx.y;
    const int b  = blockIdx.z;
    const int tid  = threadIdx.x;
    const int wid  = tid >> 5;
    const int lane = tid & 31;
    const int fr = lane >> 2;
    const int fk = (lane & 3) * 2;
    const int wr = wid * 16;

    const size_t bh = (size_t)(b*NH + h);
    const __nv_bfloat16* gQ  = g_Qbf + bh*SEQ*HE;
    const __nv_bfloat16* gK  = g_Kbf + bh*SEQ*HE;
    const __nv_bfloat16* gVh = g_Vhi + bh*SEQ*HE;
    const __nv_bfloat16* gVl = g_Vlo + bh*SEQ*HE;

    // ---- stage Q (64x64) into sK region, extract a-frags ----
    #pragma unroll
    for (int it = 0; it < 4; it++) {
        int idx = tid + it * 128;            // 512 uint4
        int r = idx >> 3, c8 = (idx & 7) * 8;
        *(uint4*)&sK[r*SKQ + c8] = *(const uint4*)(gQ + (size_t)(q0 + r)*HE + c8);
    }
    __syncthreads();
    uint32_t qa[4][4];
    #pragma unroll
    for (int kt = 0; kt < 4; kt++) {
        const __nv_bfloat16* pa = &sK[(wr + fr)*SKQ + kt*16 + fk];
        qa[kt][0] = *(const uint32_t*)(pa);
        qa[kt][1] = *(const uint32_t*)(pa + 8*SKQ);
        qa[kt][2] = *(const uint32_t*)(pa + 8);
        qa[kt][3] = *(const uint32_t*)(pa + 8*SKQ + 8);
    }
    __syncthreads();

    float oacc[8][4] = {};
    float mrow[2] = {-1e30f, -1e30f};
    float lrow[2] = {0.f, 0.f};

    for (int t = 0; t < SEQ/128; t++) {
        // ---- stage K [128 kv][64 e] ----
        #pragma unroll
        for (int it = 0; it < 8; it++) {
            int idx = tid + it * 128;        // 1024 uint4
            int r = idx >> 3, c8 = (idx & 7) * 8;
            *(uint4*)&sK[r*SKQ + c8] = *(const uint4*)(gK + (size_t)(t*128 + r)*HE + c8);
        }
        // ---- stage V hi/lo with transpose: global [s][e] -> smem [e][s] ----
        #pragma unroll
        for (int it = 0; it < 4; it++) {
            int task = tid + it * 128;       // 512 tasks: (s2 pair, e8 group)
            int e8 = task & 7;
            int s2 = task >> 3;
            const __nv_bfloat16* p0 = gVh + (size_t)(t*128 + 2*s2)*HE + e8*8;
            uint4 r0 = *(const uint4*)(p0);
            uint4 r1 = *(const uint4*)(p0 + HE);
            const __nv_bfloat16* a0 = (const __nv_bfloat16*)&r0;
            const __nv_bfloat16* a1 = (const __nv_bfloat16*)&r1;
            #pragma unroll
            for (int e = 0; e < 8; e++)
                *(__nv_bfloat162*)&sVh[(e8*8 + e)*SVP + 2*s2] = __nv_bfloat162(a0[e], a1[e]);
            const __nv_bfloat16* q0p = gVl + (size_t)(t*128 + 2*s2)*HE + e8*8;
            uint4 r2 = *(const uint4*)(q0p);
            uint4 r3 = *(const uint4*)(q0p + HE);
            const __nv_bfloat16* a2 = (const __nv_bfloat16*)&r2;
            const __nv_bfloat16* a3 = (const __nv_bfloat16*)&r3;
            #pragma unroll
            for (int e = 0; e < 8; e++)
                *(__nv_bfloat162*)&sVl[(e8*8 + e)*SVP + 2*s2] = __nv_bfloat162(a2[e], a3[e]);
        }
        __syncthreads();

        // ---- scores: 16 n-tiles x 4 k-steps ----
        float sc[16][4];
        #pragma unroll
        for (int nt = 0; nt < 16; nt++) {
            sc[nt][0] = sc[nt][1] = sc[nt][2] = sc[nt][3] = 0.f;
            #pragma unroll
            for (int kt = 0; kt < 4; kt++) {
                const __nv_bfloat16* pb = &sK[(nt*8 + fr)*SKQ + kt*16 + fk];
                uint32_t bfr[2];
                bfr[0] = *(const uint32_t*)(pb);
                bfr[1] = *(const uint32_t*)(pb + 8);
                mma16816(sc[nt], qa[kt], bfr);
            }
        }

        // ---- online softmax (rows fr, fr+8; quad shfl) ----
        float tm0 = -1e30f, tm1 = -1e30f;
        #pragma unroll
        for (int nt = 0; nt < 16; nt++) {
            tm0 = fmaxf(tm0, fmaxf(sc[nt][0], sc[nt][1]));
            tm1 = fmaxf(tm1, fmaxf(sc[nt][2], sc[nt][3]));
        }
        #pragma unroll
        for (int off = 1; off <= 2; off <<= 1) {
            tm0 = fmaxf(tm0, __shfl_xor_sync(0xffffffffu, tm0, off));
            tm1 = fmaxf(tm1, __shfl_xor_sync(0xffffffffu, tm1, off));
        }
        float nm0 = fmaxf(mrow[0], tm0), nm1 = fmaxf(mrow[1], tm1);
        float corr0 = __expf(mrow[0] - nm0), corr1 = __expf(mrow[1] - nm1);
        float rs0 = 0.f, rs1 = 0.f;
        #pragma unroll
        for (int nt = 0; nt < 16; nt++) {
            sc[nt][0] = __expf(sc[nt][0] - nm0);
            sc[nt][1] = __expf(sc[nt][1] - nm0);
            sc[nt][2] = __expf(sc[nt][2] - nm1);
            sc[nt][3] = __expf(sc[nt][3] - nm1);
            rs0 += sc[nt][0] + sc[nt][1];
            rs1 += sc[nt][2] + sc[nt][3];
        }
        #pragma unroll
        for (int off = 1; off <= 2; off <<= 1) {
            rs0 += __shfl_xor_sync(0xffffffffu, rs0, off);
            rs1 += __shfl_xor_sync(0xffffffffu, rs1, off);
        }
        lrow[0] = lrow[0]*corr0 + rs0;
        lrow[1] = lrow[1]*corr1 + rs1;
        mrow[0] = nm0; mrow[1] = nm1;
        #pragma unroll
        for (int nt = 0; nt < 8; nt++) {
            oacc[nt][0] *= corr0; oacc[nt][1] *= corr0;
            oacc[nt][2] *= corr1; oacc[nt][3] *= corr1;
        }

        // ---- PV: O += P @ V, 3-term split ----
        #pragma unroll
        for (int kt2 = 0; kt2 < 8; kt2++) {
            uint32_t phi[4], plo[4];
            {
                __nv_bfloat16 h0,l0,h1,l1;
                split_bf16(sc[2*kt2][0], h0, l0); split_bf16(sc[2*kt2][1], h1, l1);
                phi[0] = pack_bf2(h0,h1); plo[0] = pack_bf2(l0,l1);
                split_bf16(sc[2*kt2][2], h0, l0); split_bf16(sc[2*kt2][3], h1, l1);
                phi[1] = pack_bf2(h0,h1); plo[1] = pack_bf2(l0,l1);
                split_bf16(sc[2*kt2+1][0], h0, l0); split_bf16(sc[2*kt2+1][1], h1, l1);
                phi[2] = pack_bf2(h0,h1); plo[2] = pack_bf2(l0,l1);
                split_bf16(sc[2*kt2+1][2], h0, l0); split_bf16(sc[2*kt2+1][3], h1, l1);
                phi[3] = pack_bf2(h0,h1); plo[3] = pack_bf2(l0,l1);
            }
            #pragma unroll
            for (int nt2 = 0; nt2 < 8; nt2++) {
                const __nv_bfloat16* pbh = &sVh[(nt2*8 + fr)*SVP + kt2*16 + fk];
                const __nv_bfloat16* pbl = &sVl[(nt2*8 + fr)*SVP + kt2*16 + fk];
                uint32_t bh[2], bl[2];
                bh[0] = *(const uint32_t*)(pbh); bh[1] = *(const uint32_t*)(pbh + 8);
                bl[0] = *(const uint32_t*)(pbl); bl[1] = *(const uint32_t*)(pbl + 8);
                mma16816(oacc[nt2], phi, bh);
                mma16816(oacc[nt2], phi, bl);
                mma16816(oacc[nt2], plo, bh);
            }
        }
        __syncthreads();
    }

    // ---- epilogue: normalize, write g_ATT [b,s,h*e] fp32 ----
    float inv0 = 1.0f / lrow[0], inv1 = 1.0f / lrow[1];
    int row0 = q0 + wr + fr;
    #pragma unroll
    for (int nt2 = 0; nt2 < 8; nt2++) {
        int e = nt2*8 + fk;
        *(float2*)(g_ATT + ((size_t)(b*SEQ + row0))*(NH*HE) + h*HE + e) =
            make_float2(oacc[nt2][0]*inv0, oacc[nt2][1]*inv0);
        *(float2*)(g_ATT + ((size_t)(b*SEQ + row0 + 8))*(NH*HE) + h*HE + e) =
            make_float2(oacc[nt2][2]*inv1, oacc[nt2][3]*inv1);
    }
}

// ---------------------------------------------------------------------------
extern "C" void kernel_launch(void* const* d_in, const int* in_sizes, int n_in,
                              void* d_out, int out_size)
{
    const float* query = (const float*)d_in[0];
    const float* key   = (const float*)d_in[1];
    const float* value = (const float*)d_in[2];
    const float* Wq    = (const float*)d_in[3];
    const float* Wk    = (const float*)d_in[4];
    const float* Wv    = (const float*)d_in[5];
    const float* Wo    = (const float*)d_in[6];
    const float* bo    = (const float*)d_in[7];
    float* out = (float*)d_out;

    cudaFuncSetAttribute(attn_mma, cudaFuncAttributeMaxDynamicSharedMemorySize, SM_ATT);

    dim3 gg(MROWS/TM, (NH*HE)/TN);   // (64, 8)

    gemm_mma<0><<<gg, 256>>>(query, Wq, nullptr, nullptr);
    gemm_mma<1><<<gg, 256>>>(key,   Wk, nullptr, nullptr);
    gemm_mma<2><<<gg, 256>>>(value, Wv, nullptr, nullptr);

    attn_mma<<<dim3(SEQ/64, NH, BB), 128, SM_ATT>>>();

    gemm_mma<3><<<dim3(MROWS/TM, DOUT/TN), 256>>>(nullptr, Wo, bo, out);
}

// round 6
// speedup vs baseline: 3.0566x; 1.4203x over previous
#include <cuda_runtime.h>
#include <cuda_bf16.h>
#include <cstdint>

#define BB   8
#define SEQ  1024
#define DQKV 1024
#define NH   16
#define HE   64
#define DOUT 1024
#define MROWS 8192

#define TM 128
#define TN 128
#define TK 32
#define SP 40
#define NCH (DQKV/TK)     // 32
#define TILE_B (TM*SP*2)  // 10240 bytes per tile
#define BUF_B  (4*TILE_B) // 40960 bytes per buffer
#define SMEM_G (2*BUF_B)  // 81920

// ---- device scratch (allocation-free contract) ----
__device__ __nv_bfloat16 g_Xh[3*MROWS*DQKV];     // split X (q,k,v inputs)
__device__ __nv_bfloat16 g_Xl[3*MROWS*DQKV];
__device__ __nv_bfloat16 g_WTh[3*DQKV*DQKV];     // W^T [n=h*64+e][k], split
__device__ __nv_bfloat16 g_WTl[3*DQKV*DQKV];
__device__ __nv_bfloat16 g_Woh[DOUT*DQKV];       // Wo [out][k], split
__device__ __nv_bfloat16 g_Wol[DOUT*DQKV];
__device__ __nv_bfloat16 g_Qbf[BB*NH*SEQ*HE];    // [b,h,s,e] scale folded
__device__ __nv_bfloat16 g_Kbf[BB*NH*SEQ*HE];
__device__ __nv_bfloat16 g_Vhi[BB*NH*SEQ*HE];
__device__ __nv_bfloat16 g_Vlo[BB*NH*SEQ*HE];
__device__ __nv_bfloat16 g_Ah[MROWS*DQKV];       // attention out, split [b,s,h*e]
__device__ __nv_bfloat16 g_Al[MROWS*DQKV];

__device__ __forceinline__ void split_bf16(float x, __nv_bfloat16& h, __nv_bfloat16& l) {
    h = __float2bfloat16(x);
    l = __float2bfloat16(x - __bfloat162float(h));
}

__device__ __forceinline__ void mma16816(float* d, const uint32_t* a, const uint32_t* b) {
    asm volatile(
        "mma.sync.aligned.m16n8k16.row.col.f32.bf16.bf16.f32 "
        "{%0,%1,%2,%3}, {%4,%5,%6,%7}, {%8,%9}, {%0,%1,%2,%3};"
        : "+f"(d[0]), "+f"(d[1]), "+f"(d[2]), "+f"(d[3])
        : "r"(a[0]), "r"(a[1]), "r"(a[2]), "r"(a[3]), "r"(b[0]), "r"(b[1]));
}

__device__ __forceinline__ uint32_t pack_bf2(__nv_bfloat16 lo, __nv_bfloat16 hi) {
    __nv_bfloat162 t(lo, hi);
    return *(uint32_t*)&t;
}

__device__ __forceinline__ uint32_t smem_u32(const void* p) {
    uint32_t a;
    asm("{ .reg .u64 t; cvta.to.shared.u64 t, %1; cvt.u32.u64 %0, t; }" : "=r"(a) : "l"(p));
    return a;
}
__device__ __forceinline__ void cpa16(uint32_t dst, const void* src) {
    asm volatile("cp.async.cg.shared.global [%0], [%1], 16;" :: "r"(dst), "l"(src));
}
#define CPA_COMMIT() asm volatile("cp.async.commit_group;" ::: "memory")
#define CPA_WAIT1()  asm volatile("cp.async.wait_group 1;" ::: "memory")
#define CPA_WAIT0()  asm volatile("cp.async.wait_group 0;" ::: "memory")

// ---------------------------------------------------------------------------
// Pre-pass: fp32 -> split bf16 (straight layout)
// ---------------------------------------------------------------------------
__global__ void cvt_split(const float* __restrict__ src,
                          __nv_bfloat16* __restrict__ dh,
                          __nv_bfloat16* __restrict__ dl, int n4)
{
    int i = blockIdx.x * blockDim.x + threadIdx.x;
    int st = gridDim.x * blockDim.x;
    for (; i < n4; i += st) {
        float4 v = ((const float4*)src)[i];
        __nv_bfloat16 h0,l0,h1,l1,h2,l2,h3,l3;
        split_bf16(v.x,h0,l0); split_bf16(v.y,h1,l1);
        split_bf16(v.z,h2,l2); split_bf16(v.w,h3,l3);
        ((__nv_bfloat162*)dh)[2*i]   = __nv_bfloat162(h0,h1);
        ((__nv_bfloat162*)dh)[2*i+1] = __nv_bfloat162(h2,h3);
        ((__nv_bfloat162*)dl)[2*i]   = __nv_bfloat162(l0,l1);
        ((__nv_bfloat162*)dl)[2*i+1] = __nv_bfloat162(l2,l3);
    }
}

// ---------------------------------------------------------------------------
// Pre-pass: W[p][h][k][e] -> W^T [p][(h*64+e)][k], split bf16 (tiled transpose)
// ---------------------------------------------------------------------------
__global__ __launch_bounds__(256) void cvt_wt(const float* __restrict__ Wq,
                                              const float* __restrict__ Wk,
                                              const float* __restrict__ Wv)
{
    __shared__ float t[64][65];
    const int k0 = blockIdx.x * 64;
    const int h  = blockIdx.y;
    const int p  = blockIdx.z;
    const float* W = (p == 0) ? Wq : (p == 1) ? Wk : Wv;
    __nv_bfloat16* dh = g_WTh + (size_t)p * DQKV * DQKV;
    __nv_bfloat16* dl = g_WTl + (size_t)p * DQKV * DQKV;
    const int tid = threadIdx.x;

    #pragma unroll
    for (int i = 0; i < 16; i++) {
        int idx = tid + i * 256;
        int k = idx >> 6, e = idx & 63;
        t[e][k] = W[((size_t)h * DQKV + k0 + k) * HE + e];
    }
    __syncthreads();
    #pragma unroll
    for (int i = 0; i < 16; i++) {
        int idx = tid + i * 256;
        int e = idx >> 6, k = idx & 63;
        __nv_bfloat16 hh, ll;
        split_bf16(t[e][k], hh, ll);
        size_t o = (size_t)(h * 64 + e) * DQKV + k0 + k;
        dh[o] = hh; dl[o] = ll;
    }
}

// ---------------------------------------------------------------------------
// Shared cp.async double-buffered split-bf16 GEMM mainloop (3-term)
// ---------------------------------------------------------------------------
__device__ __forceinline__ void mma_mainloop(
    const __nv_bfloat16* __restrict__ gAhi, const __nv_bfloat16* __restrict__ gAlo,
    const __nv_bfloat16* __restrict__ gBhi, const __nv_bfloat16* __restrict__ gBlo,
    int m0, int n0, char* sm, float acc[4][4][4])
{
    const int tid  = threadIdx.x;
    const int wid  = tid >> 5;
    const int lane = tid & 31;
    const int wm = (wid & 1) * 64;
    const int wn = (wid >> 1) * 32;
    const int fr = lane >> 2;
    const int fk = (lane & 3) * 2;
    const uint32_t sb = smem_u32(sm);
    const int rb = tid >> 2;           // base row 0..63
    const int cseg = (tid & 3) * 8;    // k seg offset (elems)

    auto stage = [&](int ch, int buf) {
        const int kk = ch * TK;
        const uint32_t base = sb + buf * BUF_B;
        #pragma unroll
        for (int i = 0; i < 8; i++) {
            const int tile = i >> 1;
            const int r = rb + (i & 1) * 64;
            const __nv_bfloat16* s =
                (tile == 0 ? gAhi : tile == 1 ? gAlo : tile == 2 ? gBhi : gBlo)
                + (size_t)((tile < 2 ? m0 : n0) + r) * DQKV + kk + cseg;
            uint32_t d = base + tile * TILE_B + (uint32_t)(r * SP + cseg) * 2;
            cpa16(d, s);
        }
        CPA_COMMIT();
    };

    int buf = 0;
    stage(0, 0);

    for (int ch = 0; ch < NCH; ch++) {
        if (ch + 1 < NCH) { stage(ch + 1, buf ^ 1); CPA_WAIT1(); }
        else              { CPA_WAIT0(); }
        __syncthreads();

        const __nv_bfloat16* sAhi = (const __nv_bfloat16*)(sm + buf * BUF_B);
        const __nv_bfloat16* sAlo = sAhi + TM*SP;
        const __nv_bfloat16* sBhi = sAlo + TM*SP;
        const __nv_bfloat16* sBlo = sBhi + TN*SP;

        #pragma unroll
        for (int kt = 0; kt < 2; kt++) {
            const int kb = kt * 16 + fk;
            uint32_t ah[4][4], bh[4][2];
            #pragma unroll
            for (int mt = 0; mt < 4; mt++) {
                const __nv_bfloat16* pa = &sAhi[(wm + mt*16 + fr)*SP + kb];
                ah[mt][0] = *(const uint32_t*)(pa);
                ah[mt][1] = *(const uint32_t*)(pa + 8*SP);
                ah[mt][2] = *(const uint32_t*)(pa + 8);
                ah[mt][3] = *(const uint32_t*)(pa + 8*SP + 8);
            }
            #pragma unroll
            for (int nt = 0; nt < 4; nt++) {
                const __nv_bfloat16* pb = &sBhi[(wn + nt*8 + fr)*SP + kb];
                bh[nt][0] = *(const uint32_t*)(pb);
                bh[nt][1] = *(const uint32_t*)(pb + 8);
            }
            #pragma unroll
            for (int mt = 0; mt < 4; mt++)
                #pragma unroll
                for (int nt = 0; nt < 4; nt++)
                    mma16816(acc[mt][nt], ah[mt], bh[nt]);
            {
                uint32_t bl[4][2];
                #pragma unroll
                for (int nt = 0; nt < 4; nt++) {
                    const __nv_bfloat16* pb = &sBlo[(wn + nt*8 + fr)*SP + kb];
                    bl[nt][0] = *(const uint32_t*)(pb);
                    bl[nt][1] = *(const uint32_t*)(pb + 8);
                }
                #pragma unroll
                for (int mt = 0; mt < 4; mt++)
                    #pragma unroll
                    for (int nt = 0; nt < 4; nt++)
                        mma16816(acc[mt][nt], ah[mt], bl[nt]);
            }
            {
                uint32_t al[4][4];
                #pragma unroll
                for (int mt = 0; mt < 4; mt++) {
                    const __nv_bfloat16* pa = &sAlo[(wm + mt*16 + fr)*SP + kb];
                    al[mt][0] = *(const uint32_t*)(pa);
                    al[mt][1] = *(const uint32_t*)(pa + 8*SP);
                    al[mt][2] = *(const uint32_t*)(pa + 8);
                    al[mt][3] = *(const uint32_t*)(pa + 8*SP + 8);
                }
                #pragma unroll
                for (int mt = 0; mt < 4; mt++)
                    #pragma unroll
                    for (int nt = 0; nt < 4; nt++)
                        mma16816(acc[mt][nt], al[mt], bh[nt]);
            }
        }
        __syncthreads();
        buf ^= 1;
    }
}

// ---------------------------------------------------------------------------
// QKV projection GEMM: one launch, blockIdx.z = projection index.
// ---------------------------------------------------------------------------
__global__ __launch_bounds__(256, 2) void proj_gemm()
{
    extern __shared__ char sm[];
    const int p  = blockIdx.z;
    const int m0 = blockIdx.x * TM;
    const int n0 = blockIdx.y * TN;

    const __nv_bfloat16* gAhi = g_Xh + (size_t)p * MROWS * DQKV;
    const __nv_bfloat16* gAlo = g_Xl + (size_t)p * MROWS * DQKV;
    const __nv_bfloat16* gBhi = g_WTh + (size_t)p * DQKV * DQKV;
    const __nv_bfloat16* gBlo = g_WTl + (size_t)p * DQKV * DQKV;

    float acc[4][4][4] = {};
    mma_mainloop(gAhi, gAlo, gBhi, gBlo, m0, n0, sm, acc);

    const int tid  = threadIdx.x;
    const int wid  = tid >> 5;
    const int lane = tid & 31;
    const int wm = (wid & 1) * 64;
    const int wn = (wid >> 1) * 32;
    const int fr = lane >> 2;
    const int fk = (lane & 3) * 2;
    const float qscale = 0.03125f;

    #pragma unroll
    for (int mt = 0; mt < 4; mt++) {
        #pragma unroll
        for (int nt = 0; nt < 4; nt++) {
            int row = m0 + wm + mt*16 + fr;
            int np  = n0 + wn + nt*8 + fk;
            int h = np >> 6, e = np & 63;
            int b = row >> 10, s = row & 1023;
            int r1 = row + 8;
            int b1i = r1 >> 10, s1 = r1 & 1023;
            size_t base  = ((size_t)((b*NH + h)*SEQ + s))*HE + e;
            size_t base1 = ((size_t)((b1i*NH + h)*SEQ + s1))*HE + e;
            if (p == 2) {
                __nv_bfloat16 h0,l0,h1,l1;
                split_bf16(acc[mt][nt][0], h0, l0);
                split_bf16(acc[mt][nt][1], h1, l1);
                *(__nv_bfloat162*)(g_Vhi + base) = __nv_bfloat162(h0, h1);
                *(__nv_bfloat162*)(g_Vlo + base) = __nv_bfloat162(l0, l1);
                split_bf16(acc[mt][nt][2], h0, l0);
                split_bf16(acc[mt][nt][3], h1, l1);
                *(__nv_bfloat162*)(g_Vhi + base1) = __nv_bfloat162(h0, h1);
                *(__nv_bfloat162*)(g_Vlo + base1) = __nv_bfloat162(l0, l1);
            } else {
                __nv_bfloat16* dst = (p == 0) ? g_Qbf : g_Kbf;
                float f = (p == 0) ? qscale : 1.0f;
                *(__nv_bfloat162*)(dst + base) =
                    __nv_bfloat162(__float2bfloat16(acc[mt][nt][0]*f),
                                   __float2bfloat16(acc[mt][nt][1]*f));
                *(__nv_bfloat162*)(dst + base1) =
                    __nv_bfloat162(__float2bfloat16(acc[mt][nt][2]*f),
                                   __float2bfloat16(acc[mt][nt][3]*f));
            }
        }
    }
}

// ---------------------------------------------------------------------------
// Output projection GEMM: ATT(split) @ Wo^T + bo -> fp32 out
// ---------------------------------------------------------------------------
__global__ __launch_bounds__(256, 2) void out_gemm(const float* __restrict__ bias,
                                                   float* __restrict__ outp)
{
    extern __shared__ char sm[];
    const int m0 = blockIdx.x * TM;
    const int n0 = blockIdx.y * TN;

    float acc[4][4][4] = {};
    mma_mainloop(g_Ah, g_Al, g_Woh, g_Wol, m0, n0, sm, acc);

    const int tid  = threadIdx.x;
    const int wid  = tid >> 5;
    const int lane = tid & 31;
    const int wm = (wid & 1) * 64;
    const int wn = (wid >> 1) * 32;
    const int fr = lane >> 2;
    const int fk = (lane & 3) * 2;

    #pragma unroll
    for (int mt = 0; mt < 4; mt++) {
        #pragma unroll
        for (int nt = 0; nt < 4; nt++) {
            int row = m0 + wm + mt*16 + fr;
            int np  = n0 + wn + nt*8 + fk;
            float b0 = __ldg(bias + np), b1 = __ldg(bias + np + 1);
            *(float2*)(outp + (size_t)row * DOUT + np) =
                make_float2(acc[mt][nt][0] + b0, acc[mt][nt][1] + b1);
            *(float2*)(outp + (size_t)(row + 8) * DOUT + np) =
                make_float2(acc[mt][nt][2] + b0, acc[mt][nt][3] + b1);
        }
    }
}

// ---------------------------------------------------------------------------
// Tensor-core flash attention. CTA: 64 q rows, 128 threads. KV tile = 128.
// Epilogue writes ATT split bf16.
// ---------------------------------------------------------------------------
#define SKQ 72
#define SVP 136
#define SM_K   0
#define SM_VH  (128*SKQ*2)
#define SM_VL  (SM_VH + 64*SVP*2)
#define SM_ATT (SM_VL + 64*SVP*2)     // 53248

__global__ __launch_bounds__(128) void attn_mma()
{
    extern __shared__ char sm[];
    __nv_bfloat16* sK  = (__nv_bfloat16*)(sm + SM_K);
    __nv_bfloat16* sVh = (__nv_bfloat16*)(sm + SM_VH);
    __nv_bfloat16* sVl = (__nv_bfloat16*)(sm + SM_VL);

    const int q0 = blockIdx.x * 64;
    const int h  = blockIdx.y;
    const int b  = blockIdx.z;
    const int tid  = threadIdx.x;
    const int wid  = tid >> 5;
    const int lane = tid & 31;
    const int fr = lane >> 2;
    const int fk = (lane & 3) * 2;
    const int wr = wid * 16;

    const size_t bh = (size_t)(b*NH + h);
    const __nv_bfloat16* gQ  = g_Qbf + bh*SEQ*HE;
    const __nv_bfloat16* gK  = g_Kbf + bh*SEQ*HE;
    const __nv_bfloat16* gVh = g_Vhi + bh*SEQ*HE;
    const __nv_bfloat16* gVl = g_Vlo + bh*SEQ*HE;

    #pragma unroll
    for (int it = 0; it < 4; it++) {
        int idx = tid + it * 128;
        int r = idx >> 3, c8 = (idx & 7) * 8;
        *(uint4*)&sK[r*SKQ + c8] = *(const uint4*)(gQ + (size_t)(q0 + r)*HE + c8);
    }
    __syncthreads();
    uint32_t qa[4][4];
    #pragma unroll
    for (int kt = 0; kt < 4; kt++) {
        const __nv_bfloat16* pa = &sK[(wr + fr)*SKQ + kt*16 + fk];
        qa[kt][0] = *(const uint32_t*)(pa);
        qa[kt][1] = *(const uint32_t*)(pa + 8*SKQ);
        qa[kt][2] = *(const uint32_t*)(pa + 8);
        qa[kt][3] = *(const uint32_t*)(pa + 8*SKQ + 8);
    }
    __syncthreads();

    float oacc[8][4] = {};
    float mrow[2] = {-1e30f, -1e30f};
    float lrow[2] = {0.f, 0.f};

    for (int t = 0; t < SEQ/128; t++) {
        #pragma unroll
        for (int it = 0; it < 8; it++) {
            int idx = tid + it * 128;
            int r = idx >> 3, c8 = (idx & 7) * 8;
            *(uint4*)&sK[r*SKQ + c8] = *(const uint4*)(gK + (size_t)(t*128 + r)*HE + c8);
        }
        #pragma unroll
        for (int it = 0; it < 4; it++) {
            int task = tid + it * 128;
            int e8 = task & 7;
            int s2 = task >> 3;
            const __nv_bfloat16* p0 = gVh + (size_t)(t*128 + 2*s2)*HE + e8*8;
            uint4 r0 = *(const uint4*)(p0);
            uint4 r1 = *(const uint4*)(p0 + HE);
            const __nv_bfloat16* a0 = (const __nv_bfloat16*)&r0;
            const __nv_bfloat16* a1 = (const __nv_bfloat16*)&r1;
            #pragma unroll
            for (int e = 0; e < 8; e++)
                *(__nv_bfloat162*)&sVh[(e8*8 + e)*SVP + 2*s2] = __nv_bfloat162(a0[e], a1[e]);
            const __nv_bfloat16* q0p = gVl + (size_t)(t*128 + 2*s2)*HE + e8*8;
            uint4 r2 = *(const uint4*)(q0p);
            uint4 r3 = *(const uint4*)(q0p + HE);
            const __nv_bfloat16* a2 = (const __nv_bfloat16*)&r2;
            const __nv_bfloat16* a3 = (const __nv_bfloat16*)&r3;
            #pragma unroll
            for (int e = 0; e < 8; e++)
                *(__nv_bfloat162*)&sVl[(e8*8 + e)*SVP + 2*s2] = __nv_bfloat162(a2[e], a3[e]);
        }
        __syncthreads();

        float sc[16][4];
        #pragma unroll
        for (int nt = 0; nt < 16; nt++) {
            sc[nt][0] = sc[nt][1] = sc[nt][2] = sc[nt][3] = 0.f;
            #pragma unroll
            for (int kt = 0; kt < 4; kt++) {
                const __nv_bfloat16* pb = &sK[(nt*8 + fr)*SKQ + kt*16 + fk];
                uint32_t bfr[2];
                bfr[0] = *(const uint32_t*)(pb);
                bfr[1] = *(const uint32_t*)(pb + 8);
                mma16816(sc[nt], qa[kt], bfr);
            }
        }

        float tm0 = -1e30f, tm1 = -1e30f;
        #pragma unroll
        for (int nt = 0; nt < 16; nt++) {
            tm0 = fmaxf(tm0, fmaxf(sc[nt][0], sc[nt][1]));
            tm1 = fmaxf(tm1, fmaxf(sc[nt][2], sc[nt][3]));
        }
        #pragma unroll
        for (int off = 1; off <= 2; off <<= 1) {
            tm0 = fmaxf(tm0, __shfl_xor_sync(0xffffffffu, tm0, off));
            tm1 = fmaxf(tm1, __shfl_xor_sync(0xffffffffu, tm1, off));
        }
        float nm0 = fmaxf(mrow[0], tm0), nm1 = fmaxf(mrow[1], tm1);
        float corr0 = __expf(mrow[0] - nm0), corr1 = __expf(mrow[1] - nm1);
        float rs0 = 0.f, rs1 = 0.f;
        #pragma unroll
        for (int nt = 0; nt < 16; nt++) {
            sc[nt][0] = __expf(sc[nt][0] - nm0);
            sc[nt][1] = __expf(sc[nt][1] - nm0);
            sc[nt][2] = __expf(sc[nt][2] - nm1);
            sc[nt][3] = __expf(sc[nt][3] - nm1);
            rs0 += sc[nt][0] + sc[nt][1];
            rs1 += sc[nt][2] + sc[nt][3];
        }
        #pragma unroll
        for (int off = 1; off <= 2; off <<= 1) {
            rs0 += __shfl_xor_sync(0xffffffffu, rs0, off);
            rs1 += __shfl_xor_sync(0xffffffffu, rs1, off);
        }
        lrow[0] = lrow[0]*corr0 + rs0;
        lrow[1] = lrow[1]*corr1 + rs1;
        mrow[0] = nm0; mrow[1] = nm1;
        #pragma unroll
        for (int nt = 0; nt < 8; nt++) {
            oacc[nt][0] *= corr0; oacc[nt][1] *= corr0;
            oacc[nt][2] *= corr1; oacc[nt][3] *= corr1;
        }

        #pragma unroll
        for (int kt2 = 0; kt2 < 8; kt2++) {
            uint32_t phi[4], plo[4];
            {
                __nv_bfloat16 h0,l0,h1,l1;
                split_bf16(sc[2*kt2][0], h0, l0); split_bf16(sc[2*kt2][1], h1, l1);
                phi[0] = pack_bf2(h0,h1); plo[0] = pack_bf2(l0,l1);
                split_bf16(sc[2*kt2][2], h0, l0); split_bf16(sc[2*kt2][3], h1, l1);
                phi[1] = pack_bf2(h0,h1); plo[1] = pack_bf2(l0,l1);
                split_bf16(sc[2*kt2+1][0], h0, l0); split_bf16(sc[2*kt2+1][1], h1, l1);
                phi[2] = pack_bf2(h0,h1); plo[2] = pack_bf2(l0,l1);
                split_bf16(sc[2*kt2+1][2], h0, l0); split_bf16(sc[2*kt2+1][3], h1, l1);
                phi[3] = pack_bf2(h0,h1); plo[3] = pack_bf2(l0,l1);
            }
            #pragma unroll
            for (int nt2 = 0; nt2 < 8; nt2++) {
                const __nv_bfloat16* pbh = &sVh[(nt2*8 + fr)*SVP + kt2*16 + fk];
                const __nv_bfloat16* pbl = &sVl[(nt2*8 + fr)*SVP + kt2*16 + fk];
                uint32_t bh[2], bl[2];
                bh[0] = *(const uint32_t*)(pbh); bh[1] = *(const uint32_t*)(pbh + 8);
                bl[0] = *(const uint32_t*)(pbl); bl[1] = *(const uint32_t*)(pbl + 8);
                mma16816(oacc[nt2], phi, bh);
                mma16816(oacc[nt2], phi, bl);
                mma16816(oacc[nt2], plo, bh);
            }
        }
        __syncthreads();
    }

    // ---- epilogue: normalize, write ATT as split bf16 [b,s,h*e] ----
    float inv0 = 1.0f / lrow[0], inv1 = 1.0f / lrow[1];
    int row0 = q0 + wr + fr;
    #pragma unroll
    for (int nt2 = 0; nt2 < 8; nt2++) {
        int e = nt2*8 + fk;
        size_t o0 = ((size_t)(b*SEQ + row0))*(NH*HE) + h*HE + e;
        size_t o1 = ((size_t)(b*SEQ + row0 + 8))*(NH*HE) + h*HE + e;
        __nv_bfloat16 h0,l0,h1,l1;
        split_bf16(oacc[nt2][0]*inv0, h0, l0);
        split_bf16(oacc[nt2][1]*inv0, h1, l1);
        *(__nv_bfloat162*)(g_Ah + o0) = __nv_bfloat162(h0, h1);
        *(__nv_bfloat162*)(g_Al + o0) = __nv_bfloat162(l0, l1);
        split_bf16(oacc[nt2][2]*inv1, h0, l0);
        split_bf16(oacc[nt2][3]*inv1, h1, l1);
        *(__nv_bfloat162*)(g_Ah + o1) = __nv_bfloat162(h0, h1);
        *(__nv_bfloat162*)(g_Al + o1) = __nv_bfloat162(l0, l1);
    }
}

// ---------------------------------------------------------------------------
extern "C" void kernel_launch(void* const* d_in, const int* in_sizes, int n_in,
                              void* d_out, int out_size)
{
    const float* query = (const float*)d_in[0];
    const float* key   = (const float*)d_in[1];
    const float* value = (const float*)d_in[2];
    const float* Wq    = (const float*)d_in[3];
    const float* Wk    = (const float*)d_in[4];
    const float* Wv    = (const float*)d_in[5];
    const float* Wo    = (const float*)d_in[6];
    const float* bo    = (const float*)d_in[7];
    float* out = (float*)d_out;

    cudaFuncSetAttribute(proj_gemm, cudaFuncAttributeMaxDynamicSharedMemorySize, SMEM_G);
    cudaFuncSetAttribute(out_gemm,  cudaFuncAttributeMaxDynamicSharedMemorySize, SMEM_G);
    cudaFuncSetAttribute(attn_mma,  cudaFuncAttributeMaxDynamicSharedMemorySize, SM_ATT);

    // resolve device-global addresses for prepass destinations
    __nv_bfloat16 *pXh, *pXl, *pWoh, *pWol;
    cudaGetSymbolAddress((void**)&pXh,  g_Xh);
    cudaGetSymbolAddress((void**)&pXl,  g_Xl);
    cudaGetSymbolAddress((void**)&pWoh, g_Woh);
    cudaGetSymbolAddress((void**)&pWol, g_Wol);

    const int N4X = MROWS*DQKV/4;   // 2M float4
    cvt_split<<<1024, 256>>>(query, pXh,                  pXl,                  N4X);
    cvt_split<<<1024, 256>>>(key,   pXh + MROWS*DQKV,     pXl + MROWS*DQKV,     N4X);
    cvt_split<<<1024, 256>>>(value, pXh + 2*MROWS*DQKV,   pXl + 2*MROWS*DQKV,   N4X);
    cvt_split<<<512, 256>>>(Wo, pWoh, pWol, DOUT*DQKV/4);
    cvt_wt<<<dim3(16, NH, 3), 256>>>(Wq, Wk, Wv);

    proj_gemm<<<dim3(MROWS/TM, (NH*HE)/TN, 3), 256, SMEM_G>>>();

    attn_mma<<<dim3(SEQ/64, NH, BB), 128, SM_ATT>>>();

    out_gemm<<<dim3(MROWS/TM, DOUT/TN), 256, SMEM_G>>>(bo, out);
}

// round 7
// speedup vs baseline: 3.3787x; 1.1054x over previous
#include <cuda_runtime.h>
#include <cuda_bf16.h>
#include <cstdint>

#define BB   8
#define SEQ  1024
#define DQKV 1024
#define NH   16
#define HE   64
#define DOUT 1024
#define MROWS 8192

#define TM 128
#define TN 128
#define TK 32
#define SP 40
#define NCH (DQKV/TK)     // 32
#define TILE_B (TM*SP*2)  // 10240 bytes per tile
#define BUF_B  (4*TILE_B) // 40960 bytes per buffer
#define SMEM_G (2*BUF_B)  // 81920

// ---- device scratch (allocation-free contract) ----
__device__ __nv_bfloat16 g_Xh[3*MROWS*DQKV];
__device__ __nv_bfloat16 g_Xl[3*MROWS*DQKV];
__device__ __nv_bfloat16 g_WTh[3*DQKV*DQKV];
__device__ __nv_bfloat16 g_WTl[3*DQKV*DQKV];
__device__ __nv_bfloat16 g_Woh[DOUT*DQKV];
__device__ __nv_bfloat16 g_Wol[DOUT*DQKV];
__device__ __nv_bfloat16 g_Qbf[BB*NH*SEQ*HE];   // scale*log2e folded
__device__ __nv_bfloat16 g_Kbf[BB*NH*SEQ*HE];
__device__ __nv_bfloat16 g_Vhi[BB*NH*SEQ*HE];
__device__ __nv_bfloat16 g_Vlo[BB*NH*SEQ*HE];
__device__ __nv_bfloat16 g_Ah[MROWS*DQKV];
__device__ __nv_bfloat16 g_Al[MROWS*DQKV];

__device__ __forceinline__ void split_bf16(float x, __nv_bfloat16& h, __nv_bfloat16& l) {
    h = __float2bfloat16(x);
    l = __float2bfloat16(x - __bfloat162float(h));
}

__device__ __forceinline__ float ex2(float x) {
    float y;
    asm("ex2.approx.ftz.f32 %0, %1;" : "=f"(y) : "f"(x));
    return y;
}

__device__ __forceinline__ void mma16816(float* d, const uint32_t* a, const uint32_t* b) {
    asm volatile(
        "mma.sync.aligned.m16n8k16.row.col.f32.bf16.bf16.f32 "
        "{%0,%1,%2,%3}, {%4,%5,%6,%7}, {%8,%9}, {%0,%1,%2,%3};"
        : "+f"(d[0]), "+f"(d[1]), "+f"(d[2]), "+f"(d[3])
        : "r"(a[0]), "r"(a[1]), "r"(a[2]), "r"(a[3]), "r"(b[0]), "r"(b[1]));
}

__device__ __forceinline__ uint32_t pack_bf2(__nv_bfloat16 lo, __nv_bfloat16 hi) {
    __nv_bfloat162 t(lo, hi);
    return *(uint32_t*)&t;
}

__device__ __forceinline__ uint32_t smem_u32(const void* p) {
    uint32_t a;
    asm("{ .reg .u64 t; cvta.to.shared.u64 t, %1; cvt.u32.u64 %0, t; }" : "=r"(a) : "l"(p));
    return a;
}
__device__ __forceinline__ void cpa16(uint32_t dst, const void* src) {
    asm volatile("cp.async.cg.shared.global [%0], [%1], 16;" :: "r"(dst), "l"(src));
}
#define CPA_COMMIT() asm volatile("cp.async.commit_group;" ::: "memory")
#define CPA_WAIT1()  asm volatile("cp.async.wait_group 1;" ::: "memory")
#define CPA_WAIT0()  asm volatile("cp.async.wait_group 0;" ::: "memory")

// ---------------------------------------------------------------------------
// Pre-pass: fp32 -> split bf16 (X q,k,v in one launch via grid.z)
// ---------------------------------------------------------------------------
__global__ void cvt_split3(const float* __restrict__ s0, const float* __restrict__ s1,
                           const float* __restrict__ s2,
                           __nv_bfloat16* __restrict__ dh,
                           __nv_bfloat16* __restrict__ dl, int n4)
{
    const int p = blockIdx.z;
    const float* src = (p == 0) ? s0 : (p == 1) ? s1 : s2;
    __nv_bfloat16* dhp = dh + (size_t)p * MROWS * DQKV;
    __nv_bfloat16* dlp = dl + (size_t)p * MROWS * DQKV;
    int i = blockIdx.x * blockDim.x + threadIdx.x;
    int st = gridDim.x * blockDim.x;
    for (; i < n4; i += st) {
        float4 v = ((const float4*)src)[i];
        __nv_bfloat16 h0,l0,h1,l1,h2,l2,h3,l3;
        split_bf16(v.x,h0,l0); split_bf16(v.y,h1,l1);
        split_bf16(v.z,h2,l2); split_bf16(v.w,h3,l3);
        ((__nv_bfloat162*)dhp)[2*i]   = __nv_bfloat162(h0,h1);
        ((__nv_bfloat162*)dhp)[2*i+1] = __nv_bfloat162(h2,h3);
        ((__nv_bfloat162*)dlp)[2*i]   = __nv_bfloat162(l0,l1);
        ((__nv_bfloat162*)dlp)[2*i+1] = __nv_bfloat162(l2,l3);
    }
}

__global__ void cvt_split(const float* __restrict__ src,
                          __nv_bfloat16* __restrict__ dh,
                          __nv_bfloat16* __restrict__ dl, int n4)
{
    int i = blockIdx.x * blockDim.x + threadIdx.x;
    int st = gridDim.x * blockDim.x;
    for (; i < n4; i += st) {
        float4 v = ((const float4*)src)[i];
        __nv_bfloat16 h0,l0,h1,l1,h2,l2,h3,l3;
        split_bf16(v.x,h0,l0); split_bf16(v.y,h1,l1);
        split_bf16(v.z,h2,l2); split_bf16(v.w,h3,l3);
        ((__nv_bfloat162*)dh)[2*i]   = __nv_bfloat162(h0,h1);
        ((__nv_bfloat162*)dh)[2*i+1] = __nv_bfloat162(h2,h3);
        ((__nv_bfloat162*)dl)[2*i]   = __nv_bfloat162(l0,l1);
        ((__nv_bfloat162*)dl)[2*i+1] = __nv_bfloat162(l2,l3);
    }
}

// ---------------------------------------------------------------------------
// Pre-pass: W[p][h][k][e] -> W^T [p][(h*64+e)][k], split bf16
// ---------------------------------------------------------------------------
__global__ __launch_bounds__(256) void cvt_wt(const float* __restrict__ Wq,
                                              const float* __restrict__ Wk,
                                              const float* __restrict__ Wv)
{
    __shared__ float t[64][65];
    const int k0 = blockIdx.x * 64;
    const int h  = blockIdx.y;
    const int p  = blockIdx.z;
    const float* W = (p == 0) ? Wq : (p == 1) ? Wk : Wv;
    __nv_bfloat16* dh = g_WTh + (size_t)p * DQKV * DQKV;
    __nv_bfloat16* dl = g_WTl + (size_t)p * DQKV * DQKV;
    const int tid = threadIdx.x;

    #pragma unroll
    for (int i = 0; i < 16; i++) {
        int idx = tid + i * 256;
        int k = idx >> 6, e = idx & 63;
        t[e][k] = W[((size_t)h * DQKV + k0 + k) * HE + e];
    }
    __syncthreads();
    #pragma unroll
    for (int i = 0; i < 16; i++) {
        int idx = tid + i * 256;
        int e = idx >> 6, k = idx & 63;
        __nv_bfloat16 hh, ll;
        split_bf16(t[e][k], hh, ll);
        size_t o = (size_t)(h * 64 + e) * DQKV + k0 + k;
        dh[o] = hh; dl[o] = ll;
    }
}

// ---------------------------------------------------------------------------
// Shared cp.async double-buffered split-bf16 GEMM mainloop (3-term)
// ---------------------------------------------------------------------------
__device__ __forceinline__ void mma_mainloop(
    const __nv_bfloat16* __restrict__ gAhi, const __nv_bfloat16* __restrict__ gAlo,
    const __nv_bfloat16* __restrict__ gBhi, const __nv_bfloat16* __restrict__ gBlo,
    int m0, int n0, char* sm, float acc[4][4][4])
{
    const int tid  = threadIdx.x;
    const int wid  = tid >> 5;
    const int lane = tid & 31;
    const int wm = (wid & 1) * 64;
    const int wn = (wid >> 1) * 32;
    const int fr = lane >> 2;
    const int fk = (lane & 3) * 2;
    const uint32_t sb = smem_u32(sm);
    const int rb = tid >> 2;
    const int cseg = (tid & 3) * 8;

    auto stage = [&](int ch, int buf) {
        const int kk = ch * TK;
        const uint32_t base = sb + buf * BUF_B;
        #pragma unroll
        for (int i = 0; i < 8; i++) {
            const int tile = i >> 1;
            const int r = rb + (i & 1) * 64;
            const __nv_bfloat16* s =
                (tile == 0 ? gAhi : tile == 1 ? gAlo : tile == 2 ? gBhi : gBlo)
                + (size_t)((tile < 2 ? m0 : n0) + r) * DQKV + kk + cseg;
            uint32_t d = base + tile * TILE_B + (uint32_t)(r * SP + cseg) * 2;
            cpa16(d, s);
        }
        CPA_COMMIT();
    };

    int buf = 0;
    stage(0, 0);

    for (int ch = 0; ch < NCH; ch++) {
        if (ch + 1 < NCH) { stage(ch + 1, buf ^ 1); CPA_WAIT1(); }
        else              { CPA_WAIT0(); }
        __syncthreads();

        const __nv_bfloat16* sAhi = (const __nv_bfloat16*)(sm + buf * BUF_B);
        const __nv_bfloat16* sAlo = sAhi + TM*SP;
        const __nv_bfloat16* sBhi = sAlo + TM*SP;
        const __nv_bfloat16* sBlo = sBhi + TN*SP;

        #pragma unroll
        for (int kt = 0; kt < 2; kt++) {
            const int kb = kt * 16 + fk;
            uint32_t ah[4][4], bh[4][2];
            #pragma unroll
            for (int mt = 0; mt < 4; mt++) {
                const __nv_bfloat16* pa = &sAhi[(wm + mt*16 + fr)*SP + kb];
                ah[mt][0] = *(const uint32_t*)(pa);
                ah[mt][1] = *(const uint32_t*)(pa + 8*SP);
                ah[mt][2] = *(const uint32_t*)(pa + 8);
                ah[mt][3] = *(const uint32_t*)(pa + 8*SP + 8);
            }
            #pragma unroll
            for (int nt = 0; nt < 4; nt++) {
                const __nv_bfloat16* pb = &sBhi[(wn + nt*8 + fr)*SP + kb];
                bh[nt][0] = *(const uint32_t*)(pb);
                bh[nt][1] = *(const uint32_t*)(pb + 8);
            }
            #pragma unroll
            for (int mt = 0; mt < 4; mt++)
                #pragma unroll
                for (int nt = 0; nt < 4; nt++)
                    mma16816(acc[mt][nt], ah[mt], bh[nt]);
            {
                uint32_t bl[4][2];
                #pragma unroll
                for (int nt = 0; nt < 4; nt++) {
                    const __nv_bfloat16* pb = &sBlo[(wn + nt*8 + fr)*SP + kb];
                    bl[nt][0] = *(const uint32_t*)(pb);
                    bl[nt][1] = *(const uint32_t*)(pb + 8);
                }
                #pragma unroll
                for (int mt = 0; mt < 4; mt++)
                    #pragma unroll
                    for (int nt = 0; nt < 4; nt++)
                        mma16816(acc[mt][nt], ah[mt], bl[nt]);
            }
            {
                uint32_t al[4][4];
                #pragma unroll
                for (int mt = 0; mt < 4; mt++) {
                    const __nv_bfloat16* pa = &sAlo[(wm + mt*16 + fr)*SP + kb];
                    al[mt][0] = *(const uint32_t*)(pa);
                    al[mt][1] = *(const uint32_t*)(pa + 8*SP);
                    al[mt][2] = *(const uint32_t*)(pa + 8);
                    al[mt][3] = *(const uint32_t*)(pa + 8*SP + 8);
                }
                #pragma unroll
                for (int mt = 0; mt < 4; mt++)
                    #pragma unroll
                    for (int nt = 0; nt < 4; nt++)
                        mma16816(acc[mt][nt], al[mt], bh[nt]);
            }
        }
        __syncthreads();
        buf ^= 1;
    }
}

// ---------------------------------------------------------------------------
// QKV projection GEMM. grid: x = N-tiles (8), y = M-tiles (64), z = projection.
// ---------------------------------------------------------------------------
__global__ __launch_bounds__(256, 2) void proj_gemm()
{
    extern __shared__ char sm[];
    const int p  = blockIdx.z;
    const int m0 = blockIdx.y * TM;
    const int n0 = blockIdx.x * TN;

    const __nv_bfloat16* gAhi = g_Xh + (size_t)p * MROWS * DQKV;
    const __nv_bfloat16* gAlo = g_Xl + (size_t)p * MROWS * DQKV;
    const __nv_bfloat16* gBhi = g_WTh + (size_t)p * DQKV * DQKV;
    const __nv_bfloat16* gBlo = g_WTl + (size_t)p * DQKV * DQKV;

    float acc[4][4][4] = {};
    mma_mainloop(gAhi, gAlo, gBhi, gBlo, m0, n0, sm, acc);

    const int tid  = threadIdx.x;
    const int wid  = tid >> 5;
    const int lane = tid & 31;
    const int wm = (wid & 1) * 64;
    const int wn = (wid >> 1) * 32;
    const int fr = lane >> 2;
    const int fk = (lane & 3) * 2;
    const float qscale = 0.03125f * 1.44269504089f;   // 1/sqrt(1024) * log2(e)

    #pragma unroll
    for (int mt = 0; mt < 4; mt++) {
        #pragma unroll
        for (int nt = 0; nt < 4; nt++) {
            int row = m0 + wm + mt*16 + fr;
            int np  = n0 + wn + nt*8 + fk;
            int h = np >> 6, e = np & 63;
            int b = row >> 10, s = row & 1023;
            int r1 = row + 8;
            int b1i = r1 >> 10, s1 = r1 & 1023;
            size_t base  = ((size_t)((b*NH + h)*SEQ + s))*HE + e;
            size_t base1 = ((size_t)((b1i*NH + h)*SEQ + s1))*HE + e;
            if (p == 2) {
                __nv_bfloat16 h0,l0,h1,l1;
                split_bf16(acc[mt][nt][0], h0, l0);
                split_bf16(acc[mt][nt][1], h1, l1);
                *(__nv_bfloat162*)(g_Vhi + base) = __nv_bfloat162(h0, h1);
                *(__nv_bfloat162*)(g_Vlo + base) = __nv_bfloat162(l0, l1);
                split_bf16(acc[mt][nt][2], h0, l0);
                split_bf16(acc[mt][nt][3], h1, l1);
                *(__nv_bfloat162*)(g_Vhi + base1) = __nv_bfloat162(h0, h1);
                *(__nv_bfloat162*)(g_Vlo + base1) = __nv_bfloat162(l0, l1);
            } else {
                __nv_bfloat16* dst = (p == 0) ? g_Qbf : g_Kbf;
                float f = (p == 0) ? qscale : 1.0f;
                *(__nv_bfloat162*)(dst + base) =
                    __nv_bfloat162(__float2bfloat16(acc[mt][nt][0]*f),
                                   __float2bfloat16(acc[mt][nt][1]*f));
                *(__nv_bfloat162*)(dst + base1) =
                    __nv_bfloat162(__float2bfloat16(acc[mt][nt][2]*f),
                                   __float2bfloat16(acc[mt][nt][3]*f));
            }
        }
    }
}

// ---------------------------------------------------------------------------
// Output projection GEMM. grid: x = N-tiles, y = M-tiles.
// ---------------------------------------------------------------------------
__global__ __launch_bounds__(256, 2) void out_gemm(const float* __restrict__ bias,
                                                   float* __restrict__ outp)
{
    extern __shared__ char sm[];
    const int m0 = blockIdx.y * TM;
    const int n0 = blockIdx.x * TN;

    float acc[4][4][4] = {};
    mma_mainloop(g_Ah, g_Al, g_Woh, g_Wol, m0, n0, sm, acc);

    const int tid  = threadIdx.x;
    const int wid  = tid >> 5;
    const int lane = tid & 31;
    const int wm = (wid & 1) * 64;
    const int wn = (wid >> 1) * 32;
    const int fr = lane >> 2;
    const int fk = (lane & 3) * 2;

    #pragma unroll
    for (int mt = 0; mt < 4; mt++) {
        #pragma unroll
        for (int nt = 0; nt < 4; nt++) {
            int row = m0 + wm + mt*16 + fr;
            int np  = n0 + wn + nt*8 + fk;
            float b0 = __ldg(bias + np), b1 = __ldg(bias + np + 1);
            *(float2*)(outp + (size_t)row * DOUT + np) =
                make_float2(acc[mt][nt][0] + b0, acc[mt][nt][1] + b1);
            *(float2*)(outp + (size_t)(row + 8) * DOUT + np) =
                make_float2(acc[mt][nt][2] + b0, acc[mt][nt][3] + b1);
        }
    }
}

// ---------------------------------------------------------------------------
// Tensor-core flash attention. CTA: 64 q rows, 128 threads. KV tile = 128.
// V smem XOR-swizzled (conflict-free STS + LDS). Base-2 softmax.
// ---------------------------------------------------------------------------
#define SKQ 72
#define SVP 136
#define SM_K   0
#define SM_VH  (128*SKQ*2)
#define SM_VL  (SM_VH + 64*SVP*2)
#define SM_ATT (SM_VL + 64*SVP*2)     // 53248

__global__ __launch_bounds__(128) void attn_mma()
{
    extern __shared__ char sm[];
    __nv_bfloat16* sK  = (__nv_bfloat16*)(sm + SM_K);
    __nv_bfloat16* sVh = (__nv_bfloat16*)(sm + SM_VH);
    __nv_bfloat16* sVl = (__nv_bfloat16*)(sm + SM_VL);

    const int q0 = blockIdx.x * 64;
    const int h  = blockIdx.y;
    const int b  = blockIdx.z;
    const int tid  = threadIdx.x;
    const int wid  = tid >> 5;
    const int lane = tid & 31;
    const int fr = lane >> 2;
    const int fk = (lane & 3) * 2;
    const int wr = wid * 16;

    const size_t bh = (size_t)(b*NH + h);
    const __nv_bfloat16* gQ  = g_Qbf + bh*SEQ*HE;
    const __nv_bfloat16* gK  = g_Kbf + bh*SEQ*HE;
    const __nv_bfloat16* gVh = g_Vhi + bh*SEQ*HE;
    const __nv_bfloat16* gVl = g_Vlo + bh*SEQ*HE;

    #pragma unroll
    for (int it = 0; it < 4; it++) {
        int idx = tid + it * 128;
        int r = idx >> 3, c8 = (idx & 7) * 8;
        *(uint4*)&sK[r*SKQ + c8] = *(const uint4*)(gQ + (size_t)(q0 + r)*HE + c8);
    }
    __syncthreads();
    uint32_t qa[4][4];
    #pragma unroll
    for (int kt = 0; kt < 4; kt++) {
        const __nv_bfloat16* pa = &sK[(wr + fr)*SKQ + kt*16 + fk];
        qa[kt][0] = *(const uint32_t*)(pa);
        qa[kt][1] = *(const uint32_t*)(pa + 8*SKQ);
        qa[kt][2] = *(const uint32_t*)(pa + 8);
        qa[kt][3] = *(const uint32_t*)(pa + 8*SKQ + 8);
    }
    __syncthreads();

    float oacc[8][4] = {};
    float mrow[2] = {-1e30f, -1e30f};
    float lrow[2] = {0.f, 0.f};

    for (int t = 0; t < SEQ/128; t++) {
        #pragma unroll
        for (int it = 0; it < 8; it++) {
            int idx = tid + it * 128;
            int r = idx >> 3, c8 = (idx & 7) * 8;
            *(uint4*)&sK[r*SKQ + c8] = *(const uint4*)(gK + (size_t)(t*128 + r)*HE + c8);
        }
        // V staging with XOR swizzle: physical col = col ^ ((row>>3)<<3)
        #pragma unroll
        for (int it = 0; it < 4; it++) {
            int task = tid + it * 128;
            int e8 = task & 7;
            int s2 = task >> 3;
            int colp = (2*s2) ^ (e8 << 3);
            const __nv_bfloat16* p0 = gVh + (size_t)(t*128 + 2*s2)*HE + e8*8;
            uint4 r0 = *(const uint4*)(p0);
            uint4 r1 = *(const uint4*)(p0 + HE);
            const __nv_bfloat16* a0 = (const __nv_bfloat16*)&r0;
            const __nv_bfloat16* a1 = (const __nv_bfloat16*)&r1;
            #pragma unroll
            for (int e = 0; e < 8; e++)
                *(__nv_bfloat162*)&sVh[(e8*8 + e)*SVP + colp] = __nv_bfloat162(a0[e], a1[e]);
            const __nv_bfloat16* q0p = gVl + (size_t)(t*128 + 2*s2)*HE + e8*8;
            uint4 r2 = *(const uint4*)(q0p);
            uint4 r3 = *(const uint4*)(q0p + HE);
            const __nv_bfloat16* a2 = (const __nv_bfloat16*)&r2;
            const __nv_bfloat16* a3 = (const __nv_bfloat16*)&r3;
            #pragma unroll
            for (int e = 0; e < 8; e++)
                *(__nv_bfloat162*)&sVl[(e8*8 + e)*SVP + colp] = __nv_bfloat162(a2[e], a3[e]);
        }
        __syncthreads();

        float sc[16][4];
        #pragma unroll
        for (int nt = 0; nt < 16; nt++) {
            sc[nt][0] = sc[nt][1] = sc[nt][2] = sc[nt][3] = 0.f;
            #pragma unroll
            for (int kt = 0; kt < 4; kt++) {
                const __nv_bfloat16* pb = &sK[(nt*8 + fr)*SKQ + kt*16 + fk];
                uint32_t bfr[2];
                bfr[0] = *(const uint32_t*)(pb);
                bfr[1] = *(const uint32_t*)(pb + 8);
                mma16816(sc[nt], qa[kt], bfr);
            }
        }

        float tm0 = -1e30f, tm1 = -1e30f;
        #pragma unroll
        for (int nt = 0; nt < 16; nt++) {
            tm0 = fmaxf(tm0, fmaxf(sc[nt][0], sc[nt][1]));
            tm1 = fmaxf(tm1, fmaxf(sc[nt][2], sc[nt][3]));
        }
        #pragma unroll
        for (int off = 1; off <= 2; off <<= 1) {
            tm0 = fmaxf(tm0, __shfl_xor_sync(0xffffffffu, tm0, off));
            tm1 = fmaxf(tm1, __shfl_xor_sync(0xffffffffu, tm1, off));
        }
        float nm0 = fmaxf(mrow[0], tm0), nm1 = fmaxf(mrow[1], tm1);
        float corr0 = ex2(mrow[0] - nm0), corr1 = ex2(mrow[1] - nm1);
        float rs0 = 0.f, rs1 = 0.f;
        #pragma unroll
        for (int nt = 0; nt < 16; nt++) {
            sc[nt][0] = ex2(sc[nt][0] - nm0);
            sc[nt][1] = ex2(sc[nt][1] - nm0);
            sc[nt][2] = ex2(sc[nt][2] - nm1);
            sc[nt][3] = ex2(sc[nt][3] - nm1);
            rs0 += sc[nt][0] + sc[nt][1];
            rs1 += sc[nt][2] + sc[nt][3];
        }
        #pragma unroll
        for (int off = 1; off <= 2; off <<= 1) {
            rs0 += __shfl_xor_sync(0xffffffffu, rs0, off);
            rs1 += __shfl_xor_sync(0xffffffffu, rs1, off);
        }
        lrow[0] = lrow[0]*corr0 + rs0;
        lrow[1] = lrow[1]*corr1 + rs1;
        mrow[0] = nm0; mrow[1] = nm1;
        #pragma unroll
        for (int nt = 0; nt < 8; nt++) {
            oacc[nt][0] *= corr0; oacc[nt][1] *= corr0;
            oacc[nt][2] *= corr1; oacc[nt][3] *= corr1;
        }

        #pragma unroll
        for (int kt2 = 0; kt2 < 8; kt2++) {
            uint32_t phi[4], plo[4];
            {
                __nv_bfloat16 h0,l0,h1,l1;
                split_bf16(sc[2*kt2][0], h0, l0); split_bf16(sc[2*kt2][1], h1, l1);
                phi[0] = pack_bf2(h0,h1); plo[0] = pack_bf2(l0,l1);
                split_bf16(sc[2*kt2][2], h0, l0); split_bf16(sc[2*kt2][3], h1, l1);
                phi[1] = pack_bf2(h0,h1); plo[1] = pack_bf2(l0,l1);
                split_bf16(sc[2*kt2+1][0], h0, l0); split_bf16(sc[2*kt2+1][1], h1, l1);
                phi[2] = pack_bf2(h0,h1); plo[2] = pack_bf2(l0,l1);
                split_bf16(sc[2*kt2+1][2], h0, l0); split_bf16(sc[2*kt2+1][3], h1, l1);
                phi[3] = pack_bf2(h0,h1); plo[3] = pack_bf2(l0,l1);
            }
            #pragma unroll
            for (int nt2 = 0; nt2 < 8; nt2++) {
                const int rowb = (nt2*8 + fr)*SVP;
                const int c0 = (kt2*16 + fk)     ^ (nt2 << 3);
                const int c1 = (kt2*16 + 8 + fk) ^ (nt2 << 3);
                uint32_t bh[2], bl[2];
                bh[0] = *(const uint32_t*)&sVh[rowb + c0];
                bh[1] = *(const uint32_t*)&sVh[rowb + c1];
                bl[0] = *(const uint32_t*)&sVl[rowb + c0];
                bl[1] = *(const uint32_t*)&sVl[rowb + c1];
                mma16816(oacc[nt2], phi, bh);
                mma16816(oacc[nt2], phi, bl);
                mma16816(oacc[nt2], plo, bh);
            }
        }
        __syncthreads();
    }

    // ---- epilogue: normalize, write ATT split bf16 [b,s,h*e] ----
    float inv0 = 1.0f / lrow[0], inv1 = 1.0f / lrow[1];
    int row0 = q0 + wr + fr;
    #pragma unroll
    for (int nt2 = 0; nt2 < 8; nt2++) {
        int e = nt2*8 + fk;
        size_t o0 = ((size_t)(b*SEQ + row0))*(NH*HE) + h*HE + e;
        size_t o1 = ((size_t)(b*SEQ + row0 + 8))*(NH*HE) + h*HE + e;
        __nv_bfloat16 h0,l0,h1,l1;
        split_bf16(oacc[nt2][0]*inv0, h0, l0);
        split_bf16(oacc[nt2][1]*inv0, h1, l1);
        *(__nv_bfloat162*)(g_Ah + o0) = __nv_bfloat162(h0, h1);
        *(__nv_bfloat162*)(g_Al + o0) = __nv_bfloat162(l0, l1);
        split_bf16(oacc[nt2][2]*inv1, h0, l0);
        split_bf16(oacc[nt2][3]*inv1, h1, l1);
        *(__nv_bfloat162*)(g_Ah + o1) = __nv_bfloat162(h0, h1);
        *(__nv_bfloat162*)(g_Al + o1) = __nv_bfloat162(l0, l1);
    }
}

// ---------------------------------------------------------------------------
extern "C" void kernel_launch(void* const* d_in, const int* in_sizes, int n_in,
                              void* d_out, int out_size)
{
    const float* query = (const float*)d_in[0];
    const float* key   = (const float*)d_in[1];
    const float* value = (const float*)d_in[2];
    const float* Wq    = (const float*)d_in[3];
    const float* Wk    = (const float*)d_in[4];
    const float* Wv    = (const float*)d_in[5];
    const float* Wo    = (const float*)d_in[6];
    const float* bo    = (const float*)d_in[7];
    float* out = (float*)d_out;

    cudaFuncSetAttribute(proj_gemm, cudaFuncAttributeMaxDynamicSharedMemorySize, SMEM_G);
    cudaFuncSetAttribute(out_gemm,  cudaFuncAttributeMaxDynamicSharedMemorySize, SMEM_G);
    cudaFuncSetAttribute(attn_mma,  cudaFuncAttributeMaxDynamicSharedMemorySize, SM_ATT);

    __nv_bfloat16 *pXh, *pXl, *pWoh, *pWol;
    cudaGetSymbolAddress((void**)&pXh,  g_Xh);
    cudaGetSymbolAddress((void**)&pXl,  g_Xl);
    cudaGetSymbolAddress((void**)&pWoh, g_Woh);
    cudaGetSymbolAddress((void**)&pWol, g_Wol);

    const int N4X = MROWS*DQKV/4;
    cvt_split3<<<dim3(512, 1, 3), 256>>>(query, key, value, pXh, pXl, N4X);
    cvt_split<<<512, 256>>>(Wo, pWoh, pWol, DOUT*DQKV/4);
    cvt_wt<<<dim3(16, NH, 3), 256>>>(Wq, Wk, Wv);

    proj_gemm<<<dim3((NH*HE)/TN, MROWS/TM, 3), 256, SMEM_G>>>();

    attn_mma<<<dim3(SEQ/64, NH, BB), 128, SM_ATT>>>();

    out_gemm<<<dim3(DOUT/TN, MROWS/TM), 256, SMEM_G>>>(bo, out);
}

// round 8
// speedup vs baseline: 3.6490x; 1.0800x over previous
#include <cuda_runtime.h>
#include <cuda_bf16.h>
#include <cstdint>

#define BB   8
#define SEQ  1024
#define DQKV 1024
#define NH   16
#define HE   64
#define DOUT 1024
#define MROWS 8192

#define TM 128
#define TN 128
#define TK 32
#define SP 40
#define NCH (DQKV/TK)     // 32
#define TILE_B (TM*SP*2)  // 10240
#define BUF_B  (4*TILE_B) // 40960
#define SMEM_G (2*BUF_B)  // 81920

// ---- device scratch ----
__device__ __nv_bfloat16 g_Xh[3*MROWS*DQKV];
__device__ __nv_bfloat16 g_Xl[3*MROWS*DQKV];
__device__ __nv_bfloat16 g_WTh[3*DQKV*DQKV];
__device__ __nv_bfloat16 g_WTl[3*DQKV*DQKV];
__device__ __nv_bfloat16 g_Woh[DOUT*DQKV];
__device__ __nv_bfloat16 g_Wol[DOUT*DQKV];
__device__ __nv_bfloat16 g_Qbf[BB*NH*SEQ*HE];
__device__ __nv_bfloat16 g_Kbf[BB*NH*SEQ*HE];
__device__ __nv_bfloat16 g_Vhi[BB*NH*SEQ*HE];
__device__ __nv_bfloat16 g_Vlo[BB*NH*SEQ*HE];
__device__ __nv_bfloat16 g_Ah[MROWS*DQKV];
__device__ __nv_bfloat16 g_Al[MROWS*DQKV];

__device__ __forceinline__ void split_bf16(float x, __nv_bfloat16& h, __nv_bfloat16& l) {
    h = __float2bfloat16(x);
    l = __float2bfloat16(x - __bfloat162float(h));
}
__device__ __forceinline__ float ex2(float x) {
    float y; asm("ex2.approx.ftz.f32 %0, %1;" : "=f"(y) : "f"(x)); return y;
}
__device__ __forceinline__ void mma16816(float* d, const uint32_t* a, const uint32_t* b) {
    asm volatile(
        "mma.sync.aligned.m16n8k16.row.col.f32.bf16.bf16.f32 "
        "{%0,%1,%2,%3}, {%4,%5,%6,%7}, {%8,%9}, {%0,%1,%2,%3};"
        : "+f"(d[0]), "+f"(d[1]), "+f"(d[2]), "+f"(d[3])
        : "r"(a[0]), "r"(a[1]), "r"(a[2]), "r"(a[3]), "r"(b[0]), "r"(b[1]));
}
__device__ __forceinline__ uint32_t pack_bf2(__nv_bfloat16 lo, __nv_bfloat16 hi) {
    __nv_bfloat162 t(lo, hi); return *(uint32_t*)&t;
}
__device__ __forceinline__ uint32_t smem_u32(const void* p) {
    uint32_t a;
    asm("{ .reg .u64 t; cvta.to.shared.u64 t, %1; cvt.u32.u64 %0, t; }" : "=r"(a) : "l"(p));
    return a;
}
__device__ __forceinline__ void ldsm_x4(uint32_t* r, uint32_t addr) {
    asm volatile("ldmatrix.sync.aligned.m8n8.x4.shared.b16 {%0,%1,%2,%3}, [%4];"
        : "=r"(r[0]), "=r"(r[1]), "=r"(r[2]), "=r"(r[3]) : "r"(addr));
}
__device__ __forceinline__ void cpa16(uint32_t dst, const void* src) {
    asm volatile("cp.async.cg.shared.global [%0], [%1], 16;" :: "r"(dst), "l"(src));
}
#define CPA_COMMIT() asm volatile("cp.async.commit_group;" ::: "memory")
#define CPA_WAIT1()  asm volatile("cp.async.wait_group 1;" ::: "memory")
#define CPA_WAIT0()  asm volatile("cp.async.wait_group 0;" ::: "memory")

// ---------------------------------------------------------------------------
// Pre-passes
// ---------------------------------------------------------------------------
__global__ void cvt_split3(const float* __restrict__ s0, const float* __restrict__ s1,
                           const float* __restrict__ s2,
                           __nv_bfloat16* __restrict__ dh,
                           __nv_bfloat16* __restrict__ dl, int n4)
{
    const int p = blockIdx.z;
    const float* src = (p == 0) ? s0 : (p == 1) ? s1 : s2;
    __nv_bfloat16* dhp = dh + (size_t)p * MROWS * DQKV;
    __nv_bfloat16* dlp = dl + (size_t)p * MROWS * DQKV;
    int i = blockIdx.x * blockDim.x + threadIdx.x;
    int st = gridDim.x * blockDim.x;
    for (; i < n4; i += st) {
        float4 v = ((const float4*)src)[i];
        __nv_bfloat16 h0,l0,h1,l1,h2,l2,h3,l3;
        split_bf16(v.x,h0,l0); split_bf16(v.y,h1,l1);
        split_bf16(v.z,h2,l2); split_bf16(v.w,h3,l3);
        ((__nv_bfloat162*)dhp)[2*i]   = __nv_bfloat162(h0,h1);
        ((__nv_bfloat162*)dhp)[2*i+1] = __nv_bfloat162(h2,h3);
        ((__nv_bfloat162*)dlp)[2*i]   = __nv_bfloat162(l0,l1);
        ((__nv_bfloat162*)dlp)[2*i+1] = __nv_bfloat162(l2,l3);
    }
}

__global__ void cvt_split(const float* __restrict__ src,
                          __nv_bfloat16* __restrict__ dh,
                          __nv_bfloat16* __restrict__ dl, int n4)
{
    int i = blockIdx.x * blockDim.x + threadIdx.x;
    int st = gridDim.x * blockDim.x;
    for (; i < n4; i += st) {
        float4 v = ((const float4*)src)[i];
        __nv_bfloat16 h0,l0,h1,l1,h2,l2,h3,l3;
        split_bf16(v.x,h0,l0); split_bf16(v.y,h1,l1);
        split_bf16(v.z,h2,l2); split_bf16(v.w,h3,l3);
        ((__nv_bfloat162*)dh)[2*i]   = __nv_bfloat162(h0,h1);
        ((__nv_bfloat162*)dh)[2*i+1] = __nv_bfloat162(h2,h3);
        ((__nv_bfloat162*)dl)[2*i]   = __nv_bfloat162(l0,l1);
        ((__nv_bfloat162*)dl)[2*i+1] = __nv_bfloat162(l2,l3);
    }
}

__global__ __launch_bounds__(256) void cvt_wt(const float* __restrict__ Wq,
                                              const float* __restrict__ Wk,
                                              const float* __restrict__ Wv)
{
    __shared__ float t[64][65];
    const int k0 = blockIdx.x * 64;
    const int h  = blockIdx.y;
    const int p  = blockIdx.z;
    const float* W = (p == 0) ? Wq : (p == 1) ? Wk : Wv;
    __nv_bfloat16* dh = g_WTh + (size_t)p * DQKV * DQKV;
    __nv_bfloat16* dl = g_WTl + (size_t)p * DQKV * DQKV;
    const int tid = threadIdx.x;

    #pragma unroll
    for (int i = 0; i < 16; i++) {
        int idx = tid + i * 256;
        int k = idx >> 6, e = idx & 63;
        t[e][k] = W[((size_t)h * DQKV + k0 + k) * HE + e];
    }
    __syncthreads();
    #pragma unroll
    for (int i = 0; i < 16; i++) {
        int idx = tid + i * 256;
        int e = idx >> 6, k = idx & 63;
        __nv_bfloat16 hh, ll;
        split_bf16(t[e][k], hh, ll);
        size_t o = (size_t)(h * 64 + e) * DQKV + k0 + k;
        dh[o] = hh; dl[o] = ll;
    }
}

// ---------------------------------------------------------------------------
// cp.async double-buffered split-bf16 GEMM mainloop with ldmatrix frag loads
// ---------------------------------------------------------------------------
__device__ __forceinline__ void mma_mainloop(
    const __nv_bfloat16* __restrict__ gAhi, const __nv_bfloat16* __restrict__ gAlo,
    const __nv_bfloat16* __restrict__ gBhi, const __nv_bfloat16* __restrict__ gBlo,
    int m0, int n0, char* sm, float acc[4][4][4])
{
    const int tid  = threadIdx.x;
    const int wid  = tid >> 5;
    const int lane = tid & 31;
    const int wm = (wid & 1) * 64;
    const int wn = (wid >> 1) * 32;
    const uint32_t sb = smem_u32(sm);
    const int rb = tid >> 2;
    const int cseg = (tid & 3) * 8;

    // ldmatrix lane->address mappings
    const uint32_t aoff = (uint32_t)(((wm + (lane & 15)) * SP + (lane >> 4) * 8) * 2);
    const uint32_t boff = (uint32_t)(((wn + (lane >> 4) * 8 + (lane & 7)) * SP +
                                      ((lane >> 3) & 1) * 8) * 2);

    auto stage = [&](int ch, int buf) {
        const int kk = ch * TK;
        const uint32_t base = sb + buf * BUF_B;
        #pragma unroll
        for (int i = 0; i < 8; i++) {
            const int tile = i >> 1;
            const int r = rb + (i & 1) * 64;
            const __nv_bfloat16* s =
                (tile == 0 ? gAhi : tile == 1 ? gAlo : tile == 2 ? gBhi : gBlo)
                + (size_t)((tile < 2 ? m0 : n0) + r) * DQKV + kk + cseg;
            uint32_t d = base + tile * TILE_B + (uint32_t)(r * SP + cseg) * 2;
            cpa16(d, s);
        }
        CPA_COMMIT();
    };

    int buf = 0;
    stage(0, 0);

    for (int ch = 0; ch < NCH; ch++) {
        if (ch + 1 < NCH) { stage(ch + 1, buf ^ 1); CPA_WAIT1(); }
        else              { CPA_WAIT0(); }
        __syncthreads();

        const uint32_t base = sb + buf * BUF_B;
        const uint32_t bAhi = base + aoff;
        const uint32_t bAlo = base + TILE_B + aoff;
        const uint32_t bBhi = base + 2*TILE_B + boff;
        const uint32_t bBlo = base + 3*TILE_B + boff;

        #pragma unroll
        for (int kt = 0; kt < 2; kt++) {
            const uint32_t ko = (uint32_t)(kt * 16 * 2);
            uint32_t ah[4][4], bh[2][4];
            #pragma unroll
            for (int mt = 0; mt < 4; mt++)
                ldsm_x4(ah[mt], bAhi + (uint32_t)(mt * 16 * SP * 2) + ko);
            #pragma unroll
            for (int np = 0; np < 2; np++)
                ldsm_x4(bh[np], bBhi + (uint32_t)(np * 16 * SP * 2) + ko);
            #pragma unroll
            for (int mt = 0; mt < 4; mt++)
                #pragma unroll
                for (int nt = 0; nt < 4; nt++)
                    mma16816(acc[mt][nt], ah[mt], &bh[nt >> 1][(nt & 1) * 2]);
            {
                uint32_t bl[2][4];
                #pragma unroll
                for (int np = 0; np < 2; np++)
                    ldsm_x4(bl[np], bBlo + (uint32_t)(np * 16 * SP * 2) + ko);
                #pragma unroll
                for (int mt = 0; mt < 4; mt++)
                    #pragma unroll
                    for (int nt = 0; nt < 4; nt++)
                        mma16816(acc[mt][nt], ah[mt], &bl[nt >> 1][(nt & 1) * 2]);
            }
            {
                uint32_t al[4][4];
                #pragma unroll
                for (int mt = 0; mt < 4; mt++)
                    ldsm_x4(al[mt], bAlo + (uint32_t)(mt * 16 * SP * 2) + ko);
                #pragma unroll
                for (int mt = 0; mt < 4; mt++)
                    #pragma unroll
                    for (int nt = 0; nt < 4; nt++)
                        mma16816(acc[mt][nt], al[mt], &bh[nt >> 1][(nt & 1) * 2]);
            }
        }
        __syncthreads();
        buf ^= 1;
    }
}

// ---------------------------------------------------------------------------
__global__ __launch_bounds__(256, 2) void proj_gemm()
{
    extern __shared__ char sm[];
    const int p  = blockIdx.z;
    const int m0 = blockIdx.y * TM;
    const int n0 = blockIdx.x * TN;

    const __nv_bfloat16* gAhi = g_Xh + (size_t)p * MROWS * DQKV;
    const __nv_bfloat16* gAlo = g_Xl + (size_t)p * MROWS * DQKV;
    const __nv_bfloat16* gBhi = g_WTh + (size_t)p * DQKV * DQKV;
    const __nv_bfloat16* gBlo = g_WTl + (size_t)p * DQKV * DQKV;

    float acc[4][4][4] = {};
    mma_mainloop(gAhi, gAlo, gBhi, gBlo, m0, n0, sm, acc);

    const int tid  = threadIdx.x;
    const int wid  = tid >> 5;
    const int lane = tid & 31;
    const int wm = (wid & 1) * 64;
    const int wn = (wid >> 1) * 32;
    const int fr = lane >> 2;
    const int fk = (lane & 3) * 2;
    const float qscale = 0.03125f * 1.44269504089f;

    #pragma unroll
    for (int mt = 0; mt < 4; mt++) {
        #pragma unroll
        for (int nt = 0; nt < 4; nt++) {
            int row = m0 + wm + mt*16 + fr;
            int np  = n0 + wn + nt*8 + fk;
            int h = np >> 6, e = np & 63;
            int b = row >> 10, s = row & 1023;
            int r1 = row + 8;
            int b1i = r1 >> 10, s1 = r1 & 1023;
            size_t base  = ((size_t)((b*NH + h)*SEQ + s))*HE + e;
            size_t base1 = ((size_t)((b1i*NH + h)*SEQ + s1))*HE + e;
            if (p == 2) {
                __nv_bfloat16 h0,l0,h1,l1;
                split_bf16(acc[mt][nt][0], h0, l0);
                split_bf16(acc[mt][nt][1], h1, l1);
                *(__nv_bfloat162*)(g_Vhi + base) = __nv_bfloat162(h0, h1);
                *(__nv_bfloat162*)(g_Vlo + base) = __nv_bfloat162(l0, l1);
                split_bf16(acc[mt][nt][2], h0, l0);
                split_bf16(acc[mt][nt][3], h1, l1);
                *(__nv_bfloat162*)(g_Vhi + base1) = __nv_bfloat162(h0, h1);
                *(__nv_bfloat162*)(g_Vlo + base1) = __nv_bfloat162(l0, l1);
            } else {
                __nv_bfloat16* dst = (p == 0) ? g_Qbf : g_Kbf;
                float f = (p == 0) ? qscale : 1.0f;
                *(__nv_bfloat162*)(dst + base) =
                    __nv_bfloat162(__float2bfloat16(acc[mt][nt][0]*f),
                                   __float2bfloat16(acc[mt][nt][1]*f));
                *(__nv_bfloat162*)(dst + base1) =
                    __nv_bfloat162(__float2bfloat16(acc[mt][nt][2]*f),
                                   __float2bfloat16(acc[mt][nt][3]*f));
            }
        }
    }
}

__global__ __launch_bounds__(256, 2) void out_gemm(const float* __restrict__ bias,
                                                   float* __restrict__ outp)
{
    extern __shared__ char sm[];
    const int m0 = blockIdx.y * TM;
    const int n0 = blockIdx.x * TN;

    float acc[4][4][4] = {};
    mma_mainloop(g_Ah, g_Al, g_Woh, g_Wol, m0, n0, sm, acc);

    const int tid  = threadIdx.x;
    const int wid  = tid >> 5;
    const int lane = tid & 31;
    const int wm = (wid & 1) * 64;
    const int wn = (wid >> 1) * 32;
    const int fr = lane >> 2;
    const int fk = (lane & 3) * 2;

    #pragma unroll
    for (int mt = 0; mt < 4; mt++) {
        #pragma unroll
        for (int nt = 0; nt < 4; nt++) {
            int row = m0 + wm + mt*16 + fr;
            int np  = n0 + wn + nt*8 + fk;
            float b0 = __ldg(bias + np), b1 = __ldg(bias + np + 1);
            *(float2*)(outp + (size_t)row * DOUT + np) =
                make_float2(acc[mt][nt][0] + b0, acc[mt][nt][1] + b1);
            *(float2*)(outp + (size_t)(row + 8) * DOUT + np) =
                make_float2(acc[mt][nt][2] + b0, acc[mt][nt][3] + b1);
        }
    }
}

// ---------------------------------------------------------------------------
// Flash attention with ldmatrix frag loads.
// ---------------------------------------------------------------------------
#define SKQ 72
#define SVP 136
#define SM_K   0
#define SM_VH  (128*SKQ*2)
#define SM_VL  (SM_VH + 64*SVP*2)
#define SM_ATT (SM_VL + 64*SVP*2)     // 53248

__global__ __launch_bounds__(128) void attn_mma()
{
    extern __shared__ char sm[];
    __nv_bfloat16* sK  = (__nv_bfloat16*)(sm + SM_K);
    __nv_bfloat16* sVh = (__nv_bfloat16*)(sm + SM_VH);
    __nv_bfloat16* sVl = (__nv_bfloat16*)(sm + SM_VL);

    const int q0 = blockIdx.x * 64;
    const int h  = blockIdx.y;
    const int b  = blockIdx.z;
    const int tid  = threadIdx.x;
    const int wid  = tid >> 5;
    const int lane = tid & 31;
    const int fr = lane >> 2;
    const int fk = (lane & 3) * 2;
    const int wr = wid * 16;

    const uint32_t sKb  = smem_u32(sK);
    const uint32_t sVhb = smem_u32(sVh);
    const uint32_t sVlb = smem_u32(sVl);

    // ldmatrix lane mappings
    const uint32_t qoff = (uint32_t)(((wr + (lane & 15)) * SKQ + (lane >> 4) * 8) * 2);
    const int b_nt  = lane >> 4;           // 0/1 within pair
    const int b_row = lane & 7;
    const int b_seg = ((lane >> 3) & 1) * 8;
    const uint32_t koff = (uint32_t)(((b_nt * 8 + b_row) * SKQ + b_seg) * 2);

    const size_t bh = (size_t)(b*NH + h);
    const __nv_bfloat16* gQ  = g_Qbf + bh*SEQ*HE;
    const __nv_bfloat16* gK  = g_Kbf + bh*SEQ*HE;
    const __nv_bfloat16* gVh = g_Vhi + bh*SEQ*HE;
    const __nv_bfloat16* gVl = g_Vlo + bh*SEQ*HE;

    #pragma unroll
    for (int it = 0; it < 4; it++) {
        int idx = tid + it * 128;
        int r = idx >> 3, c8 = (idx & 7) * 8;
        *(uint4*)&sK[r*SKQ + c8] = *(const uint4*)(gQ + (size_t)(q0 + r)*HE + c8);
    }
    __syncthreads();
    uint32_t qa[4][4];
    #pragma unroll
    for (int kt = 0; kt < 4; kt++)
        ldsm_x4(qa[kt], sKb + qoff + (uint32_t)(kt * 16 * 2));
    __syncthreads();

    float oacc[8][4] = {};
    float mrow[2] = {-1e30f, -1e30f};
    float lrow[2] = {0.f, 0.f};

    for (int t = 0; t < SEQ/128; t++) {
        #pragma unroll
        for (int it = 0; it < 8; it++) {
            int idx = tid + it * 128;
            int r = idx >> 3, c8 = (idx & 7) * 8;
            *(uint4*)&sK[r*SKQ + c8] = *(const uint4*)(gK + (size_t)(t*128 + r)*HE + c8);
        }
        #pragma unroll
        for (int it = 0; it < 4; it++) {
            int task = tid + it * 128;
            int e8 = task & 7;
            int s2 = task >> 3;
            int colp = (2*s2) ^ (e8 << 3);
            const __nv_bfloat16* p0 = gVh + (size_t)(t*128 + 2*s2)*HE + e8*8;
            uint4 r0 = *(const uint4*)(p0);
            uint4 r1 = *(const uint4*)(p0 + HE);
            const __nv_bfloat16* a0 = (const __nv_bfloat16*)&r0;
            const __nv_bfloat16* a1 = (const __nv_bfloat16*)&r1;
            #pragma unroll
            for (int e = 0; e < 8; e++)
                *(__nv_bfloat162*)&sVh[(e8*8 + e)*SVP + colp] = __nv_bfloat162(a0[e], a1[e]);
            const __nv_bfloat16* q0p = gVl + (size_t)(t*128 + 2*s2)*HE + e8*8;
            uint4 r2 = *(const uint4*)(q0p);
            uint4 r3 = *(const uint4*)(q0p + HE);
            const __nv_bfloat16* a2 = (const __nv_bfloat16*)&r2;
            const __nv_bfloat16* a3 = (const __nv_bfloat16*)&r3;
            #pragma unroll
            for (int e = 0; e < 8; e++)
                *(__nv_bfloat162*)&sVl[(e8*8 + e)*SVP + colp] = __nv_bfloat162(a2[e], a3[e]);
        }
        __syncthreads();

        // ---- scores: 8 nt-pairs x 4 kt, ldmatrix x4 b-frags ----
        float sc[16][4];
        #pragma unroll
        for (int ntp = 0; ntp < 8; ntp++) {
            sc[2*ntp][0] = sc[2*ntp][1] = sc[2*ntp][2] = sc[2*ntp][3] = 0.f;
            sc[2*ntp+1][0] = sc[2*ntp+1][1] = sc[2*ntp+1][2] = sc[2*ntp+1][3] = 0.f;
            #pragma unroll
            for (int kt = 0; kt < 4; kt++) {
                uint32_t bfr[4];
                ldsm_x4(bfr, sKb + koff + (uint32_t)((ntp * 16 * SKQ + kt * 16) * 2));
                mma16816(sc[2*ntp],   qa[kt], &bfr[0]);
                mma16816(sc[2*ntp+1], qa[kt], &bfr[2]);
            }
        }

        float tm0 = -1e30f, tm1 = -1e30f;
        #pragma unroll
        for (int nt = 0; nt < 16; nt++) {
            tm0 = fmaxf(tm0, fmaxf(sc[nt][0], sc[nt][1]));
            tm1 = fmaxf(tm1, fmaxf(sc[nt][2], sc[nt][3]));
        }
        #pragma unroll
        for (int off = 1; off <= 2; off <<= 1) {
            tm0 = fmaxf(tm0, __shfl_xor_sync(0xffffffffu, tm0, off));
            tm1 = fmaxf(tm1, __shfl_xor_sync(0xffffffffu, tm1, off));
        }
        float nm0 = fmaxf(mrow[0], tm0), nm1 = fmaxf(mrow[1], tm1);
        float corr0 = ex2(mrow[0] - nm0), corr1 = ex2(mrow[1] - nm1);
        float rs0 = 0.f, rs1 = 0.f;
        #pragma unroll
        for (int nt = 0; nt < 16; nt++) {
            sc[nt][0] = ex2(sc[nt][0] - nm0);
            sc[nt][1] = ex2(sc[nt][1] - nm0);
            sc[nt][2] = ex2(sc[nt][2] - nm1);
            sc[nt][3] = ex2(sc[nt][3] - nm1);
            rs0 += sc[nt][0] + sc[nt][1];
            rs1 += sc[nt][2] + sc[nt][3];
        }
        #pragma unroll
        for (int off = 1; off <= 2; off <<= 1) {
            rs0 += __shfl_xor_sync(0xffffffffu, rs0, off);
            rs1 += __shfl_xor_sync(0xffffffffu, rs1, off);
        }
        lrow[0] = lrow[0]*corr0 + rs0;
        lrow[1] = lrow[1]*corr1 + rs1;
        mrow[0] = nm0; mrow[1] = nm1;
        #pragma unroll
        for (int nt = 0; nt < 8; nt++) {
            oacc[nt][0] *= corr0; oacc[nt][1] *= corr0;
            oacc[nt][2] *= corr1; oacc[nt][3] *= corr1;
        }

        // ---- PV: ldmatrix x4 V-frags (nt2 pairs), swizzled addresses ----
        #pragma unroll
        for (int kt2 = 0; kt2 < 8; kt2++) {
            uint32_t phi[4], plo[4];
            {
                __nv_bfloat16 h0,l0,h1,l1;
                split_bf16(sc[2*kt2][0], h0, l0); split_bf16(sc[2*kt2][1], h1, l1);
                phi[0] = pack_bf2(h0,h1); plo[0] = pack_bf2(l0,l1);
                split_bf16(sc[2*kt2][2], h0, l0); split_bf16(sc[2*kt2][3], h1, l1);
                phi[1] = pack_bf2(h0,h1); plo[1] = pack_bf2(l0,l1);
                split_bf16(sc[2*kt2+1][0], h0, l0); split_bf16(sc[2*kt2+1][1], h1, l1);
                phi[2] = pack_bf2(h0,h1); plo[2] = pack_bf2(l0,l1);
                split_bf16(sc[2*kt2+1][2], h0, l0); split_bf16(sc[2*kt2+1][3], h1, l1);
                phi[3] = pack_bf2(h0,h1); plo[3] = pack_bf2(l0,l1);
            }
            #pragma unroll
            for (int ntp = 0; ntp < 4; ntp++) {
                const int nt2 = ntp * 2 + b_nt;
                const uint32_t voff =
                    (uint32_t)(((nt2 * 8 + b_row) * SVP +
                                ((kt2 * 16 + b_seg) ^ (nt2 << 3))) * 2);
                uint32_t bhf[4], blf[4];
                ldsm_x4(bhf, sVhb + voff);
                ldsm_x4(blf, sVlb + voff);
                mma16816(oacc[2*ntp],   phi, &bhf[0]);
                mma16816(oacc[2*ntp],   phi, &blf[0]);
                mma16816(oacc[2*ntp],   plo, &bhf[0]);
                mma16816(oacc[2*ntp+1], phi, &bhf[2]);
                mma16816(oacc[2*ntp+1], phi, &blf[2]);
                mma16816(oacc[2*ntp+1], plo, &bhf[2]);
            }
        }
        __syncthreads();
    }

    float inv0 = 1.0f / lrow[0], inv1 = 1.0f / lrow[1];
    int row0 = q0 + wr + fr;
    #pragma unroll
    for (int nt2 = 0; nt2 < 8; nt2++) {
        int e = nt2*8 + fk;
        size_t o0 = ((size_t)(b*SEQ + row0))*(NH*HE) + h*HE + e;
        size_t o1 = ((size_t)(b*SEQ + row0 + 8))*(NH*HE) + h*HE + e;
        __nv_bfloat16 h0,l0,h1,l1;
        split_bf16(oacc[nt2][0]*inv0, h0, l0);
        split_bf16(oacc[nt2][1]*inv0, h1, l1);
        *(__nv_bfloat162*)(g_Ah + o0) = __nv_bfloat162(h0, h1);
        *(__nv_bfloat162*)(g_Al + o0) = __nv_bfloat162(l0, l1);
        split_bf16(oacc[nt2][2]*inv1, h0, l0);
        split_bf16(oacc[nt2][3]*inv1, h1, l1);
        *(__nv_bfloat162*)(g_Ah + o1) = __nv_bfloat162(h0, h1);
        *(__nv_bfloat162*)(g_Al + o1) = __nv_bfloat162(l0, l1);
    }
}

// ---------------------------------------------------------------------------
extern "C" void kernel_launch(void* const* d_in, const int* in_sizes, int n_in,
                              void* d_out, int out_size)
{
    const float* query = (const float*)d_in[0];
    const float* key   = (const float*)d_in[1];
    const float* value = (const float*)d_in[2];
    const float* Wq    = (const float*)d_in[3];
    const float* Wk    = (const float*)d_in[4];
    const float* Wv    = (const float*)d_in[5];
    const float* Wo    = (const float*)d_in[6];
    const float* bo    = (const float*)d_in[7];
    float* out = (float*)d_out;

    cudaFuncSetAttribute(proj_gemm, cudaFuncAttributeMaxDynamicSharedMemorySize, SMEM_G);
    cudaFuncSetAttribute(out_gemm,  cudaFuncAttributeMaxDynamicSharedMemorySize, SMEM_G);
    cudaFuncSetAttribute(attn_mma,  cudaFuncAttributeMaxDynamicSharedMemorySize, SM_ATT);

    __nv_bfloat16 *pXh, *pXl, *pWoh, *pWol;
    cudaGetSymbolAddress((void**)&pXh,  g_Xh);
    cudaGetSymbolAddress((void**)&pXl,  g_Xl);
    cudaGetSymbolAddress((void**)&pWoh, g_Woh);
    cudaGetSymbolAddress((void**)&pWol, g_Wol);

    const int N4X = MROWS*DQKV/4;
    cvt_split3<<<dim3(512, 1, 3), 256>>>(query, key, value, pXh, pXl, N4X);
    cvt_split<<<512, 256>>>(Wo, pWoh, pWol, DOUT*DQKV/4);
    cvt_wt<<<dim3(16, NH, 3), 256>>>(Wq, Wk, Wv);

    proj_gemm<<<dim3((NH*HE)/TN, MROWS/TM, 3), 256, SMEM_G>>>();

    attn_mma<<<dim3(SEQ/64, NH, BB), 128, SM_ATT>>>();

    out_gemm<<<dim3(DOUT/TN, MROWS/TM), 256, SMEM_G>>>(bo, out);
}